// round 1
// baseline (speedup 1.0000x reference)
#include <cuda_runtime.h>
#include <math.h>

// Problem constants (fixed shapes from reference)
#define B_ 8
#define S_ 2048
#define D_ 1024
#define F_ 4096

// Scratch: a = x@W1, b = x@W3, then h = gelu(a)*b reuses g_bufA.
__device__ float g_bufA[(size_t)B_ * S_ * F_];   // 256 MB
__device__ float g_bufB[(size_t)B_ * S_ * F_];   // 256 MB

// ---------------- SGEMM: C[b] = A[b] @ W[e(b)]  (row-major everywhere) ----------------
// A: [M,K] (k contiguous), W: [K,N] (n contiguous), C: [M,N]
#define BM 128
#define BN 128
#define BK 8
#define TM 8
#define TN 8

__global__ __launch_bounds__(256, 2)
void sgemm_expert_kernel(const float* __restrict__ A,
                         const float* __restrict__ Wbase,
                         float* __restrict__ C,
                         const int* __restrict__ langs,
                         int M, int K, int N,
                         long aBatch, long wExpert, long cBatch,
                         int scaleMode)
{
    __shared__ float As[BK][BM];   // transposed A tile: As[k][m]
    __shared__ float Bs[BK][BN];

    const int b = blockIdx.z;
    const int lang = langs[b];
    int e = lang - 4;
    if (e < 0) e = 0;
    if (e > 7) e = 7;

    float rw = 1.0f;
    if (scaleMode) {
        int cnt = (lang > 3) ? 1 : 0;
        rw = (cnt == 0) ? 1.0f : (1.0f / (float)cnt);
    }

    const float* __restrict__ Ab = A + (long)b * aBatch;
    const float* __restrict__ Bw = Wbase + (long)e * wExpert;
    float* __restrict__ Cb = C + (long)b * cBatch;

    const int tid = threadIdx.x;
    const int tx = tid & 15;        // 0..15
    const int ty = tid >> 4;        // 0..15
    const int m0 = blockIdx.y * BM;
    const int n0 = blockIdx.x * BN;
    const int tm0 = ty * TM;
    const int tn0 = tx * TN;

    // Global-load assignments (one float4 each for A and B tiles)
    const int arow = tid >> 1;          // 0..127
    const int acol = (tid & 1) * 4;     // 0 or 4
    const int brow = tid >> 5;          // 0..7
    const int bcol = (tid & 31) * 4;    // 0..124

    const float* aPtr = Ab + (long)(m0 + arow) * K + acol;   // advances by +kb along K
    const float* bPtr = Bw + (long)brow * N + n0 + bcol;     // advances by +kb*N

    float acc[TM][TN];
#pragma unroll
    for (int i = 0; i < TM; i++)
#pragma unroll
        for (int j = 0; j < TN; j++) acc[i][j] = 0.0f;

    float4 aReg = *(const float4*)aPtr;
    float4 bReg = *(const float4*)bPtr;

    for (int kb = 0; kb < K; kb += BK) {
        // Commit prefetched tile to shared
        As[acol + 0][arow] = aReg.x;
        As[acol + 1][arow] = aReg.y;
        As[acol + 2][arow] = aReg.z;
        As[acol + 3][arow] = aReg.w;
        *(float4*)&Bs[brow][bcol] = bReg;
        __syncthreads();

        // Prefetch next tile while computing on the current one
        if (kb + BK < K) {
            aReg = *(const float4*)(aPtr + (kb + BK));
            bReg = *(const float4*)(bPtr + (long)(kb + BK) * N);
        }

#pragma unroll
        for (int k = 0; k < BK; k++) {
            float4 a0 = *(const float4*)&As[k][tm0];
            float4 a1 = *(const float4*)&As[k][tm0 + 4];
            float4 b0 = *(const float4*)&Bs[k][tn0];
            float4 b1 = *(const float4*)&Bs[k][tn0 + 4];
            float av[TM] = {a0.x, a0.y, a0.z, a0.w, a1.x, a1.y, a1.z, a1.w};
            float bv[TN] = {b0.x, b0.y, b0.z, b0.w, b1.x, b1.y, b1.z, b1.w};
#pragma unroll
            for (int i = 0; i < TM; i++)
#pragma unroll
                for (int j = 0; j < TN; j++)
                    acc[i][j] = fmaf(av[i], bv[j], acc[i][j]);
        }
        __syncthreads();
    }

    // Epilogue: vectorized stores (optionally scaled by routing weight)
#pragma unroll
    for (int i = 0; i < TM; i++) {
        long row = (long)(m0 + tm0 + i) * N + n0 + tn0;
        float4 v0 = make_float4(acc[i][0], acc[i][1], acc[i][2], acc[i][3]);
        float4 v1 = make_float4(acc[i][4], acc[i][5], acc[i][6], acc[i][7]);
        if (scaleMode) {
            v0.x *= rw; v0.y *= rw; v0.z *= rw; v0.w *= rw;
            v1.x *= rw; v1.y *= rw; v1.z *= rw; v1.w *= rw;
        }
        *(float4*)&Cb[row]     = v0;
        *(float4*)&Cb[row + 4] = v1;
    }
}

// ---------------- Elementwise: h = gelu_exact(a) * b  (h written into a's buffer) ----------------
__global__ __launch_bounds__(256)
void glu_kernel(const float* __restrict__ a, const float* __restrict__ bb,
                float* __restrict__ h, size_t n4)
{
    size_t i = (size_t)blockIdx.x * blockDim.x + threadIdx.x;
    if (i >= n4) return;
    float4 av = ((const float4*)a)[i];
    float4 bv = ((const float4*)bb)[i];
    const float inv_sqrt2 = 0.70710678118654752440f;
    float4 r;
    r.x = 0.5f * av.x * (1.0f + erff(av.x * inv_sqrt2)) * bv.x;
    r.y = 0.5f * av.y * (1.0f + erff(av.y * inv_sqrt2)) * bv.y;
    r.z = 0.5f * av.z * (1.0f + erff(av.z * inv_sqrt2)) * bv.z;
    r.w = 0.5f * av.w * (1.0f + erff(av.w * inv_sqrt2)) * bv.w;
    ((float4*)h)[i] = r;
}

// ---------------- Launch ----------------
extern "C" void kernel_launch(void* const* d_in, const int* in_sizes, int n_in,
                              void* d_out, int out_size)
{
    // metadata order: hidden_states, w1, w2, w3, langs
    const float* x     = (const float*)d_in[0];   // [B,S,D]
    const float* w1    = (const float*)d_in[1];   // [E,D,F]
    const float* w2    = (const float*)d_in[2];   // [E,F,D]
    const float* w3    = (const float*)d_in[3];   // [E,D,F]
    const int*   langs = (const int*)  d_in[4];   // [B,1]
    float* out = (float*)d_out;                   // [B,S,D]

    float* bufA = nullptr;
    float* bufB = nullptr;
    cudaGetSymbolAddress((void**)&bufA, g_bufA);
    cudaGetSymbolAddress((void**)&bufB, g_bufB);

    dim3 blk(256);

    // GEMM 1: a = x @ W1   [S,D]x[D,F] per batch
    {
        dim3 grid(F_ / BN, S_ / BM, B_);
        sgemm_expert_kernel<<<grid, blk>>>(x, w1, bufA, langs,
                                           S_, D_, F_,
                                           (long)S_ * D_, (long)D_ * F_, (long)S_ * F_, 0);
    }
    // GEMM 2: b = x @ W3
    {
        dim3 grid(F_ / BN, S_ / BM, B_);
        sgemm_expert_kernel<<<grid, blk>>>(x, w3, bufB, langs,
                                           S_, D_, F_,
                                           (long)S_ * D_, (long)D_ * F_, (long)S_ * F_, 0);
    }
    // Elementwise: h = gelu(a) * b   (into bufA)
    {
        size_t n4 = ((size_t)B_ * S_ * F_) / 4;   // 16,777,216
        dim3 grid((unsigned)((n4 + 255) / 256));
        glu_kernel<<<grid, blk>>>(bufA, bufB, bufA, n4);
    }
    // GEMM 3: out = (h @ W2) * rw   [S,F]x[F,D] per batch
    {
        dim3 grid(D_ / BN, S_ / BM, B_);
        sgemm_expert_kernel<<<grid, blk>>>(bufA, w2, out, langs,
                                           S_, F_, D_,
                                           (long)S_ * F_, (long)F_ * D_, (long)S_ * D_, 1);
    }
}

// round 3
// speedup vs baseline: 1.9318x; 1.9318x over previous
#include <cuda_runtime.h>
#include <cuda_bf16.h>
#include <math.h>
#include <stdint.h>

// ---------------------------------------------------------------------------
// Problem constants
// ---------------------------------------------------------------------------
#define B_ 8
#define S_ 2048
#define D_ 1024
#define F_ 4096
#define E_ 8

// ---------------------------------------------------------------------------
// Scratch (__device__ globals; no runtime allocation allowed)
// ---------------------------------------------------------------------------
__device__ __nv_bfloat16 g_xhi[(size_t)B_ * S_ * D_];
__device__ __nv_bfloat16 g_xlo[(size_t)B_ * S_ * D_];
__device__ __nv_bfloat16 g_w1hi[(size_t)E_ * F_ * D_];   // transposed [E,F,D]
__device__ __nv_bfloat16 g_w1lo[(size_t)E_ * F_ * D_];
__device__ __nv_bfloat16 g_w3hi[(size_t)E_ * F_ * D_];
__device__ __nv_bfloat16 g_w3lo[(size_t)E_ * F_ * D_];
__device__ __nv_bfloat16 g_w2hi[(size_t)E_ * D_ * F_];   // transposed [E,D,F]
__device__ __nv_bfloat16 g_w2lo[(size_t)E_ * D_ * F_];
__device__ float         g_a[(size_t)B_ * S_ * F_];      // x@W1 fp32
__device__ __nv_bfloat16 g_hhi[(size_t)B_ * S_ * F_];
__device__ __nv_bfloat16 g_hlo[(size_t)B_ * S_ * F_];

// ---------------------------------------------------------------------------
// PTX helpers (base-target-safe: cp.async / ldmatrix / mma.sync only)
// ---------------------------------------------------------------------------
__device__ __forceinline__ uint32_t smem_to_u32(const void* p) {
    uint32_t a;
    asm("{ .reg .u64 t; cvta.to.shared.u64 t, %1; cvt.u32.u64 %0, t; }" : "=r"(a) : "l"(p));
    return a;
}

#define CP_ASYNC16(saddr, gptr) \
    asm volatile("cp.async.cg.shared.global [%0], [%1], 16;" \
                 :: "r"(saddr), "l"(gptr))
#define CP_COMMIT() asm volatile("cp.async.commit_group;" ::: "memory")
#define CP_WAIT2()  asm volatile("cp.async.wait_group 2;" ::: "memory")

__device__ __forceinline__ void ldsm_x4(uint32_t& r0, uint32_t& r1, uint32_t& r2,
                                        uint32_t& r3, uint32_t addr) {
    asm volatile("ldmatrix.sync.aligned.m8n8.x4.shared.b16 {%0,%1,%2,%3}, [%4];"
                 : "=r"(r0), "=r"(r1), "=r"(r2), "=r"(r3) : "r"(addr));
}

__device__ __forceinline__ void mma_16816(float* d, const uint32_t* a,
                                          const uint32_t* b) {
    asm volatile(
        "mma.sync.aligned.m16n8k16.row.col.f32.bf16.bf16.f32 "
        "{%0,%1,%2,%3}, {%4,%5,%6,%7}, {%8,%9}, {%0,%1,%2,%3};"
        : "+f"(d[0]), "+f"(d[1]), "+f"(d[2]), "+f"(d[3])
        : "r"(a[0]), "r"(a[1]), "r"(a[2]), "r"(a[3]), "r"(b[0]), "r"(b[1]));
}

// ---------------------------------------------------------------------------
// Prep kernels
// ---------------------------------------------------------------------------
__global__ __launch_bounds__(256)
void split_x_kernel(const float* __restrict__ src,
                    __nv_bfloat16* __restrict__ hi,
                    __nv_bfloat16* __restrict__ lo, long n4)
{
    long i = (long)blockIdx.x * blockDim.x + threadIdx.x;
    if (i >= n4) return;
    float4 v = ((const float4*)src)[i];
    union { uint2 u; __nv_bfloat16 h[4]; } ph, pl;
    float vv[4] = {v.x, v.y, v.z, v.w};
#pragma unroll
    for (int j = 0; j < 4; j++) {
        __nv_bfloat16 h = __float2bfloat16(vv[j]);
        ph.h[j] = h;
        pl.h[j] = __float2bfloat16(vv[j] - __bfloat162float(h));
    }
    ((uint2*)hi)[i] = ph.u;
    ((uint2*)lo)[i] = pl.u;
}

__global__ __launch_bounds__(256)
void transpose_split_kernel(const float* __restrict__ src,
                            __nv_bfloat16* __restrict__ dhi,
                            __nv_bfloat16* __restrict__ dlo,
                            int K, int N)
{
    __shared__ float t[32][33];
    int e = blockIdx.z;
    const float* se = src + (long)e * K * N;
    int n0 = blockIdx.x * 32, k0 = blockIdx.y * 32;
    int tx = threadIdx.x, ty = threadIdx.y;
#pragma unroll
    for (int j = 0; j < 32; j += 8)
        t[ty + j][tx] = se[(long)(k0 + ty + j) * N + n0 + tx];
    __syncthreads();
    long obase = (long)e * N * K;
#pragma unroll
    for (int j = 0; j < 32; j += 8) {
        float v = t[tx][ty + j];
        long o = obase + (long)(n0 + ty + j) * K + k0 + tx;
        __nv_bfloat16 h = __float2bfloat16(v);
        dhi[o] = h;
        dlo[o] = __float2bfloat16(v - __bfloat162float(h));
    }
}

// ---------------------------------------------------------------------------
// HMMA GEMM: C[b](M,N) = A[b](M,K) @ B[e(b)](N,K)^T via bf16 hi/lo x 3 passes
//   mode 0: write fp32     mode 1: h=gelu(glu)*C -> bf16 hi/lo   mode 2: fp32*rw
// CTA 128x128x32, 8 warps (2x4), warp tile 64x32, 4-stage cp.async pipeline.
// ---------------------------------------------------------------------------
#define BM 128
#define BN 128
#define BK 32
#define STAGES 4
#define ROWSTRIDE 80                 // bytes: 64B data + 16B pad (conflict-free)
#define ARR_B (128 * ROWSTRIDE)      // 10240 per array
#define STAGE_B (4 * ARR_B)          // 40960 per stage
#define SMEM_TOTAL (STAGES * STAGE_B)

__device__ __forceinline__ void load_stage(uint32_t sbase,
                                           const __nv_bfloat16* __restrict__ Ahi,
                                           const __nv_bfloat16* __restrict__ Alo,
                                           const __nv_bfloat16* __restrict__ Bhi,
                                           const __nv_bfloat16* __restrict__ Blo,
                                           long aRow0, long bRow0, int K, int kb, int tid)
{
#pragma unroll
    for (int j = 0; j < 2; j++) {
        int idx = tid + j * 256;             // 0..511
        int row = idx >> 2;
        int c16 = idx & 3;
        uint32_t soff = (uint32_t)(row * ROWSTRIDE + c16 * 16);
        long ga = (aRow0 + row) * (long)K + kb + c16 * 8;
        long gb = (bRow0 + row) * (long)K + kb + c16 * 8;
        CP_ASYNC16(sbase + soff,               Ahi + ga);
        CP_ASYNC16(sbase + ARR_B + soff,       Alo + ga);
        CP_ASYNC16(sbase + 2 * ARR_B + soff,   Bhi + gb);
        CP_ASYNC16(sbase + 3 * ARR_B + soff,   Blo + gb);
    }
}

__global__ __launch_bounds__(256, 1)
void mma_gemm_kernel(const __nv_bfloat16* __restrict__ Ahi,
                     const __nv_bfloat16* __restrict__ Alo,
                     const __nv_bfloat16* __restrict__ Bhi,
                     const __nv_bfloat16* __restrict__ Blo,
                     const int* __restrict__ langs,
                     int M, int N, int K,
                     float* __restrict__ outF,
                     const float* __restrict__ gluSrc,
                     __nv_bfloat16* __restrict__ outHi,
                     __nv_bfloat16* __restrict__ outLo,
                     int mode)
{
    extern __shared__ char smem[];
    const uint32_t sbase = smem_to_u32(smem);

    const int tid = threadIdx.x;
    const int wid = tid >> 5;
    const int lane = tid & 31;
    const int warp_m = wid >> 2;      // 0..1
    const int warp_n = wid & 3;       // 0..3

    const int b = blockIdx.z;
    const int m0 = blockIdx.y * BM;
    const int n0 = blockIdx.x * BN;

    const int lang = langs[b];
    int e = lang - 4;
    if (e < 0) e = 0;
    if (e > 7) e = 7;
    const float rw = 1.0f;   // exactly one routed lang per row -> 1/1; keep formula:
    const float rws = ((lang > 3) ? 1.0f : 1.0f);  // = 1 either way per reference

    const long aRow0 = (long)b * M + m0;
    const long bRow0 = (long)e * N + n0;

    float acc[4][4][4];
#pragma unroll
    for (int i = 0; i < 4; i++)
#pragma unroll
        for (int j = 0; j < 4; j++)
#pragma unroll
            for (int q = 0; q < 4; q++) acc[i][j][q] = 0.0f;

    const int NC = K / BK;

    // prologue: fill 3 stages
#pragma unroll
    for (int s = 0; s < STAGES - 1; s++) {
        load_stage(sbase + s * STAGE_B, Ahi, Alo, Bhi, Blo, aRow0, bRow0, K, s * BK, tid);
        CP_COMMIT();
    }

    for (int c = 0; c < NC; ++c) {
        CP_WAIT2();
        __syncthreads();

        int cn = c + STAGES - 1;
        if (cn < NC)
            load_stage(sbase + (cn % STAGES) * STAGE_B, Ahi, Alo, Bhi, Blo,
                       aRow0, bRow0, K, cn * BK, tid);
        CP_COMMIT();

        const uint32_t stage = sbase + (c % STAGES) * STAGE_B;
#pragma unroll
        for (int ks = 0; ks < 2; ks++) {
            uint32_t ahi[4][4], alo[4][4];
#pragma unroll
            for (int mt = 0; mt < 4; mt++) {
                int row = warp_m * 64 + mt * 16 + (lane & 15);
                uint32_t off = (uint32_t)(row * ROWSTRIDE + ks * 32 + (lane >> 4) * 16);
                ldsm_x4(ahi[mt][0], ahi[mt][1], ahi[mt][2], ahi[mt][3], stage + off);
                ldsm_x4(alo[mt][0], alo[mt][1], alo[mt][2], alo[mt][3], stage + ARR_B + off);
            }
            uint32_t bhi[4][2], blo[4][2];
#pragma unroll
            for (int bt = 0; bt < 2; bt++) {
                int row = warp_n * 32 + bt * 16 + (lane & 15);
                uint32_t off = (uint32_t)(row * ROWSTRIDE + ks * 32 + (lane >> 4) * 16);
                uint32_t r0, r1, r2, r3;
                ldsm_x4(r0, r1, r2, r3, stage + 2 * ARR_B + off);
                bhi[bt * 2][0] = r0; bhi[bt * 2][1] = r2;
                bhi[bt * 2 + 1][0] = r1; bhi[bt * 2 + 1][1] = r3;
                ldsm_x4(r0, r1, r2, r3, stage + 3 * ARR_B + off);
                blo[bt * 2][0] = r0; blo[bt * 2][1] = r2;
                blo[bt * 2 + 1][0] = r1; blo[bt * 2 + 1][1] = r3;
            }
#pragma unroll
            for (int mt = 0; mt < 4; mt++)
#pragma unroll
                for (int nt = 0; nt < 4; nt++) {
                    mma_16816(acc[mt][nt], ahi[mt], bhi[nt]);
                    mma_16816(acc[mt][nt], ahi[mt], blo[nt]);
                    mma_16816(acc[mt][nt], alo[mt], bhi[nt]);
                }
        }
        __syncthreads();
    }

    // ---------------- epilogue ----------------
    const int qr = lane >> 2;          // 0..7
    const int qc = (lane & 3) * 2;     // 0,2,4,6
    const int m_base = m0 + warp_m * 64;
    const int n_base = n0 + warp_n * 32;

#pragma unroll
    for (int mt = 0; mt < 4; mt++) {
#pragma unroll
        for (int half = 0; half < 2; half++) {
            const int gm = m_base + mt * 16 + qr + half * 8;
            const long rowBase = ((long)b * M + gm) * (long)N;
#pragma unroll
            for (int nt = 0; nt < 4; nt++) {
                const int gn = n_base + nt * 8 + qc;
                const long idx = rowBase + gn;
                float c0 = acc[mt][nt][half * 2 + 0];
                float c1 = acc[mt][nt][half * 2 + 1];
                if (mode == 1) {
                    float2 av = *(const float2*)(gluSrc + idx);
                    float g0 = 0.5f * av.x * (1.0f + erff(av.x * 0.70710678118654752f));
                    float g1 = 0.5f * av.y * (1.0f + erff(av.y * 0.70710678118654752f));
                    float h0 = g0 * c0, h1 = g1 * c1;
                    __nv_bfloat16 b0 = __float2bfloat16(h0);
                    __nv_bfloat16 b1 = __float2bfloat16(h1);
                    __nv_bfloat16 l0 = __float2bfloat16(h0 - __bfloat162float(b0));
                    __nv_bfloat16 l1 = __float2bfloat16(h1 - __bfloat162float(b1));
                    union { uint32_t u; __nv_bfloat16 h[2]; } uh, ul;
                    uh.h[0] = b0; uh.h[1] = b1;
                    ul.h[0] = l0; ul.h[1] = l1;
                    *(uint32_t*)(outHi + idx) = uh.u;
                    *(uint32_t*)(outLo + idx) = ul.u;
                } else {
                    float s = (mode == 2) ? rws : 1.0f;
                    *(float2*)(outF + idx) = make_float2(c0 * s, c1 * s);
                }
            }
        }
    }
    (void)rw;
}

// ---------------------------------------------------------------------------
// Launch
// ---------------------------------------------------------------------------
extern "C" void kernel_launch(void* const* d_in, const int* in_sizes, int n_in,
                              void* d_out, int out_size)
{
    const float* x     = (const float*)d_in[0];   // [B,S,D]
    const float* w1    = (const float*)d_in[1];   // [E,D,F]
    const float* w2    = (const float*)d_in[2];   // [E,F,D]
    const float* w3    = (const float*)d_in[3];   // [E,D,F]
    const int*   langs = (const int*)  d_in[4];   // [B,1]
    float* out = (float*)d_out;                   // [B,S,D]

    __nv_bfloat16 *xhi, *xlo, *w1hi, *w1lo, *w3hi, *w3lo, *w2hi, *w2lo, *hhi, *hlo;
    float* abuf;
    cudaGetSymbolAddress((void**)&xhi,  g_xhi);
    cudaGetSymbolAddress((void**)&xlo,  g_xlo);
    cudaGetSymbolAddress((void**)&w1hi, g_w1hi);
    cudaGetSymbolAddress((void**)&w1lo, g_w1lo);
    cudaGetSymbolAddress((void**)&w3hi, g_w3hi);
    cudaGetSymbolAddress((void**)&w3lo, g_w3lo);
    cudaGetSymbolAddress((void**)&w2hi, g_w2hi);
    cudaGetSymbolAddress((void**)&w2lo, g_w2lo);
    cudaGetSymbolAddress((void**)&hhi,  g_hhi);
    cudaGetSymbolAddress((void**)&hlo,  g_hlo);
    cudaGetSymbolAddress((void**)&abuf, g_a);

    cudaFuncSetAttribute(mma_gemm_kernel,
                         cudaFuncAttributeMaxDynamicSharedMemorySize, SMEM_TOTAL);

    // 1) split x -> bf16 hi/lo
    {
        long n4 = (long)B_ * S_ * D_ / 4;
        split_x_kernel<<<(unsigned)(n4 / 256), 256>>>(x, xhi, xlo, n4);
    }
    // 2) transpose + split weights
    {
        dim3 blk(32, 8);
        dim3 g1(F_ / 32, D_ / 32, E_);
        transpose_split_kernel<<<g1, blk>>>(w1, w1hi, w1lo, D_, F_);
        transpose_split_kernel<<<g1, blk>>>(w3, w3hi, w3lo, D_, F_);
        dim3 g2(D_ / 32, F_ / 32, E_);
        transpose_split_kernel<<<g2, blk>>>(w2, w2hi, w2lo, F_, D_);
    }
    // 3) GEMM1: a = x @ W1 (fp32)
    {
        dim3 grid(F_ / BN, S_ / BM, B_);
        mma_gemm_kernel<<<grid, 256, SMEM_TOTAL>>>(
            xhi, xlo, w1hi, w1lo, langs, S_, F_, D_,
            abuf, nullptr, nullptr, nullptr, 0);
    }
    // 4) GEMM2: b = x @ W3; h = gelu(a)*b -> bf16 hi/lo
    {
        dim3 grid(F_ / BN, S_ / BM, B_);
        mma_gemm_kernel<<<grid, 256, SMEM_TOTAL>>>(
            xhi, xlo, w3hi, w3lo, langs, S_, F_, D_,
            nullptr, abuf, hhi, hlo, 1);
    }
    // 5) GEMM3: out = (h @ W2) * rw
    {
        dim3 grid(D_ / BN, S_ / BM, B_);
        mma_gemm_kernel<<<grid, 256, SMEM_TOTAL>>>(
            hhi, hlo, w2hi, w2lo, langs, S_, D_, F_,
            out, nullptr, nullptr, nullptr, 2);
    }
}

// round 4
// speedup vs baseline: 2.1064x; 1.0904x over previous
#include <cuda_runtime.h>
#include <cuda_bf16.h>
#include <math.h>
#include <stdint.h>

// ---------------------------------------------------------------------------
// Problem constants
// ---------------------------------------------------------------------------
#define B_ 8
#define S_ 2048
#define D_ 1024
#define F_ 4096
#define E_ 8

// ---------------------------------------------------------------------------
// Scratch (__device__ globals)
// ---------------------------------------------------------------------------
__device__ __nv_bfloat16 g_xhi[(size_t)B_ * S_ * D_];
__device__ __nv_bfloat16 g_xlo[(size_t)B_ * S_ * D_];
__device__ __nv_bfloat16 g_w1hi[(size_t)E_ * F_ * D_];   // transposed [E,F,D]
__device__ __nv_bfloat16 g_w1lo[(size_t)E_ * F_ * D_];
__device__ __nv_bfloat16 g_w3hi[(size_t)E_ * F_ * D_];
__device__ __nv_bfloat16 g_w3lo[(size_t)E_ * F_ * D_];
__device__ __nv_bfloat16 g_w2hi[(size_t)E_ * D_ * F_];   // transposed [E,D,F]
__device__ __nv_bfloat16 g_w2lo[(size_t)E_ * D_ * F_];
__device__ __nv_bfloat16 g_hhi[(size_t)B_ * S_ * F_];
__device__ __nv_bfloat16 g_hlo[(size_t)B_ * S_ * F_];

// ---------------------------------------------------------------------------
// PTX helpers (base-target-safe)
// ---------------------------------------------------------------------------
__device__ __forceinline__ uint32_t smem_to_u32(const void* p) {
    uint32_t a;
    asm("{ .reg .u64 t; cvta.to.shared.u64 t, %1; cvt.u32.u64 %0, t; }" : "=r"(a) : "l"(p));
    return a;
}

#define CP_ASYNC16(saddr, gptr) \
    asm volatile("cp.async.cg.shared.global [%0], [%1], 16;" :: "r"(saddr), "l"(gptr))
#define CP_COMMIT()  asm volatile("cp.async.commit_group;" ::: "memory")
#define CP_WAIT2()   asm volatile("cp.async.wait_group 2;" ::: "memory")
#define CP_WAIT0()   asm volatile("cp.async.wait_group 0;" ::: "memory")

__device__ __forceinline__ void ldsm_x4(uint32_t& r0, uint32_t& r1, uint32_t& r2,
                                        uint32_t& r3, uint32_t addr) {
    asm volatile("ldmatrix.sync.aligned.m8n8.x4.shared.b16 {%0,%1,%2,%3}, [%4];"
                 : "=r"(r0), "=r"(r1), "=r"(r2), "=r"(r3) : "r"(addr));
}

__device__ __forceinline__ void mma_16816(float* d, const uint32_t* a, const uint32_t* b) {
    asm volatile(
        "mma.sync.aligned.m16n8k16.row.col.f32.bf16.bf16.f32 "
        "{%0,%1,%2,%3}, {%4,%5,%6,%7}, {%8,%9}, {%0,%1,%2,%3};"
        : "+f"(d[0]), "+f"(d[1]), "+f"(d[2]), "+f"(d[3])
        : "r"(a[0]), "r"(a[1]), "r"(a[2]), "r"(a[3]), "r"(b[0]), "r"(b[1]));
}

// ---------------------------------------------------------------------------
// Prep kernels
// ---------------------------------------------------------------------------
__global__ __launch_bounds__(256)
void split_x_kernel(const float* __restrict__ src,
                    __nv_bfloat16* __restrict__ hi,
                    __nv_bfloat16* __restrict__ lo, long n4)
{
    long i = (long)blockIdx.x * blockDim.x + threadIdx.x;
    if (i >= n4) return;
    float4 v = ((const float4*)src)[i];
    union { uint2 u; __nv_bfloat16 h[4]; } ph, pl;
    float vv[4] = {v.x, v.y, v.z, v.w};
#pragma unroll
    for (int j = 0; j < 4; j++) {
        __nv_bfloat16 h = __float2bfloat16(vv[j]);
        ph.h[j] = h;
        pl.h[j] = __float2bfloat16(vv[j] - __bfloat162float(h));
    }
    ((uint2*)hi)[i] = ph.u;
    ((uint2*)lo)[i] = pl.u;
}

__global__ __launch_bounds__(256)
void transpose_split_kernel(const float* __restrict__ src,
                            __nv_bfloat16* __restrict__ dhi,
                            __nv_bfloat16* __restrict__ dlo,
                            int K, int N)
{
    __shared__ float t[32][33];
    int e = blockIdx.z;
    const float* se = src + (long)e * K * N;
    int n0 = blockIdx.x * 32, k0 = blockIdx.y * 32;
    int tx = threadIdx.x, ty = threadIdx.y;
#pragma unroll
    for (int j = 0; j < 32; j += 8)
        t[ty + j][tx] = se[(long)(k0 + ty + j) * N + n0 + tx];
    __syncthreads();
    long obase = (long)e * N * K;
#pragma unroll
    for (int j = 0; j < 32; j += 8) {
        float v = t[tx][ty + j];
        long o = obase + (long)(n0 + ty + j) * K + k0 + tx;
        __nv_bfloat16 h = __float2bfloat16(v);
        dhi[o] = h;
        dlo[o] = __float2bfloat16(v - __bfloat162float(h));
    }
}

// ---------------------------------------------------------------------------
// Common tiling constants
// ---------------------------------------------------------------------------
#define BK 32
#define STAGES 4
#define ROWSTRIDE 80                  // 64B data + 16B pad
#define STAGE_B 40960
#define SMEM_TOTAL (STAGES * STAGE_B) // 160 KB

// ===========================================================================
// FUSED kernel: a = x@W1^T, b = x@W3^T, h = gelu(a)*b -> bf16 hi/lo
// CTA: 128(M) x 64(N) per output; 16 warps: out_sel=wid>>3, 4(m)x2(n) of 32x32.
// Stage layout: Ahi@0, Alo@10240, B1hi@20480, B1lo@25600, B3hi@30720, B3lo@35840
// ===========================================================================
__device__ __forceinline__ void load_stage_fused(
    uint32_t st,
    const __nv_bfloat16* __restrict__ Ahi, const __nv_bfloat16* __restrict__ Alo,
    const __nv_bfloat16* __restrict__ B1hi, const __nv_bfloat16* __restrict__ B1lo,
    const __nv_bfloat16* __restrict__ B3hi, const __nv_bfloat16* __restrict__ B3lo,
    long aRow0, long bRow0, int K, int kb, int tid)
{
#pragma unroll
    for (int j = 0; j < 2; j++) {       // A: 128 rows x 4 chunks x 2 arrays
        int idx = tid + j * 512;
        int c16 = idx & 3, row = (idx >> 2) & 127, arr = idx >> 9;
        uint32_t s = st + arr * 10240 + row * ROWSTRIDE + c16 * 16;
        const __nv_bfloat16* g = (arr ? Alo : Ahi) + (aRow0 + row) * (long)K + kb + c16 * 8;
        CP_ASYNC16(s, g);
    }
#pragma unroll
    for (int j = 0; j < 2; j++) {       // B: 64 rows x 4 chunks x 4 arrays
        int idx = tid + j * 512;
        int c16 = idx & 3, row = (idx >> 2) & 63, arr = idx >> 8;   // 0..3
        uint32_t s = st + 20480 + arr * 5120 + row * ROWSTRIDE + c16 * 16;
        const __nv_bfloat16* g;
        if (arr == 0) g = B1hi; else if (arr == 1) g = B1lo;
        else if (arr == 2) g = B3hi; else g = B3lo;
        g += (bRow0 + row) * (long)K + kb + c16 * 8;
        CP_ASYNC16(s, g);
    }
}

__global__ __launch_bounds__(512, 1)
void fused_gemm12_kernel(const __nv_bfloat16* __restrict__ Ahi,
                         const __nv_bfloat16* __restrict__ Alo,
                         const __nv_bfloat16* __restrict__ B1hi,
                         const __nv_bfloat16* __restrict__ B1lo,
                         const __nv_bfloat16* __restrict__ B3hi,
                         const __nv_bfloat16* __restrict__ B3lo,
                         const int* __restrict__ langs,
                         __nv_bfloat16* __restrict__ outHi,
                         __nv_bfloat16* __restrict__ outLo)
{
    extern __shared__ char smem[];
    const uint32_t sbase = smem_to_u32(smem);

    const int tid = threadIdx.x;
    const int wid = tid >> 5;
    const int lane = tid & 31;
    const int out_sel = wid >> 3;          // 0: W1(a), 1: W3(b)
    const int w8 = wid & 7;
    const int wm = w8 >> 1;                // 0..3 (32 rows each)
    const int wn = w8 & 1;                 // 0..1 (32 cols each)

    const int bz = blockIdx.z;
    const int m0 = blockIdx.y * 128;
    const int n0 = blockIdx.x * 64;

    const int lang = langs[bz];
    int e = lang - 4;
    if (e < 0) e = 0;
    if (e > 7) e = 7;

    const long aRow0 = (long)bz * S_ + m0;
    const long bRow0 = (long)e * F_ + n0;
    const int K = D_;
    const int NC = K / BK;                 // 32

    float acc[2][4][4];
#pragma unroll
    for (int i = 0; i < 2; i++)
#pragma unroll
        for (int j = 0; j < 4; j++)
#pragma unroll
            for (int q = 0; q < 4; q++) acc[i][j][q] = 0.0f;

#pragma unroll
    for (int s = 0; s < STAGES - 1; s++) {
        load_stage_fused(sbase + s * STAGE_B, Ahi, Alo, B1hi, B1lo, B3hi, B3lo,
                         aRow0, bRow0, K, s * BK, tid);
        CP_COMMIT();
    }

    const uint32_t bArr = 20480 + out_sel * 10240;

    for (int c = 0; c < NC; ++c) {
        CP_WAIT2();
        __syncthreads();
        int cn = c + STAGES - 1;
        if (cn < NC)
            load_stage_fused(sbase + (cn % STAGES) * STAGE_B, Ahi, Alo, B1hi, B1lo,
                             B3hi, B3lo, aRow0, bRow0, K, cn * BK, tid);
        CP_COMMIT();

        const uint32_t st = sbase + (c % STAGES) * STAGE_B;
#pragma unroll
        for (int ks = 0; ks < 2; ks++) {
            uint32_t ahi[2][4], alo[2][4];
#pragma unroll
            for (int mt = 0; mt < 2; mt++) {
                int row = wm * 32 + mt * 16 + (lane & 15);
                uint32_t off = (uint32_t)(row * ROWSTRIDE + ks * 32 + (lane >> 4) * 16);
                ldsm_x4(ahi[mt][0], ahi[mt][1], ahi[mt][2], ahi[mt][3], st + off);
                ldsm_x4(alo[mt][0], alo[mt][1], alo[mt][2], alo[mt][3], st + 10240 + off);
            }
            uint32_t bhi[4][2], blo[4][2];
#pragma unroll
            for (int bt = 0; bt < 2; bt++) {
                int row = wn * 32 + bt * 16 + (lane & 15);
                uint32_t off = (uint32_t)(row * ROWSTRIDE + ks * 32 + (lane >> 4) * 16);
                uint32_t r0, r1, r2, r3;
                ldsm_x4(r0, r1, r2, r3, st + bArr + off);
                bhi[bt * 2][0] = r0; bhi[bt * 2][1] = r2;
                bhi[bt * 2 + 1][0] = r1; bhi[bt * 2 + 1][1] = r3;
                ldsm_x4(r0, r1, r2, r3, st + bArr + 5120 + off);
                blo[bt * 2][0] = r0; blo[bt * 2][1] = r2;
                blo[bt * 2 + 1][0] = r1; blo[bt * 2 + 1][1] = r3;
            }
#pragma unroll
            for (int mt = 0; mt < 2; mt++)
#pragma unroll
                for (int nt = 0; nt < 4; nt++) {
                    mma_16816(acc[mt][nt], ahi[mt], bhi[nt]);
                    mma_16816(acc[mt][nt], ahi[mt], blo[nt]);
                    mma_16816(acc[mt][nt], alo[mt], bhi[nt]);
                }
        }
        __syncthreads();
    }

    // --- epilogue: exchange a via smem, b-warps apply gelu(a)*b ---
    CP_WAIT0();
    __syncthreads();
    float* ex = (float*)smem;              // 8 warps x 1024 floats = 32 KB
    if (out_sel == 0) {
#pragma unroll
        for (int mt = 0; mt < 2; mt++)
#pragma unroll
            for (int nt = 0; nt < 4; nt++)
#pragma unroll
                for (int q = 0; q < 4; q++) {
                    int i = (mt * 4 + nt) * 4 + q;
                    ex[w8 * 1024 + i * 32 + lane] = acc[mt][nt][q];
                }
    }
    __syncthreads();
    if (out_sel == 1) {
        const int qr = lane >> 2;
        const int qc = (lane & 3) * 2;
#pragma unroll
        for (int mt = 0; mt < 2; mt++) {
#pragma unroll
            for (int half = 0; half < 2; half++) {
                const int gm = m0 + wm * 32 + mt * 16 + qr + half * 8;
                const long rowBase = ((long)bz * S_ + gm) * (long)F_;
#pragma unroll
                for (int nt = 0; nt < 4; nt++) {
                    const int gn = n0 + wn * 32 + nt * 8 + qc;
                    const long idx = rowBase + gn;
                    float b0 = acc[mt][nt][half * 2 + 0];
                    float b1 = acc[mt][nt][half * 2 + 1];
                    int i0 = (mt * 4 + nt) * 4 + half * 2;
                    float a0 = ex[w8 * 1024 + i0 * 32 + lane];
                    float a1 = ex[w8 * 1024 + (i0 + 1) * 32 + lane];
                    float g0 = 0.5f * a0 * (1.0f + erff(a0 * 0.70710678118654752f));
                    float g1 = 0.5f * a1 * (1.0f + erff(a1 * 0.70710678118654752f));
                    float h0 = g0 * b0, h1 = g1 * b1;
                    __nv_bfloat16 x0 = __float2bfloat16(h0);
                    __nv_bfloat16 x1 = __float2bfloat16(h1);
                    __nv_bfloat16 l0 = __float2bfloat16(h0 - __bfloat162float(x0));
                    __nv_bfloat16 l1 = __float2bfloat16(h1 - __bfloat162float(x1));
                    union { uint32_t u; __nv_bfloat16 h[2]; } uh, ul;
                    uh.h[0] = x0; uh.h[1] = x1;
                    ul.h[0] = l0; ul.h[1] = l1;
                    *(uint32_t*)(outHi + idx) = uh.u;
                    *(uint32_t*)(outLo + idx) = ul.u;
                }
            }
        }
    }
}

// ===========================================================================
// GEMM3: out = (h @ W2^T) * rw.  CTA 128x128, 16 warps 4x4 of 32x32.
// Stage layout: Ahi@0, Alo@10240, Bhi@20480, Blo@30720
// ===========================================================================
__device__ __forceinline__ void load_stage_g3(
    uint32_t st,
    const __nv_bfloat16* __restrict__ Ahi, const __nv_bfloat16* __restrict__ Alo,
    const __nv_bfloat16* __restrict__ Bhi, const __nv_bfloat16* __restrict__ Blo,
    long aRow0, long bRow0, int K, int kb, int tid)
{
#pragma unroll
    for (int j = 0; j < 2; j++) {
        int idx = tid + j * 512;
        int c16 = idx & 3, row = (idx >> 2) & 127, arr = idx >> 9;
        uint32_t s = st + arr * 10240 + row * ROWSTRIDE + c16 * 16;
        const __nv_bfloat16* g = (arr ? Alo : Ahi) + (aRow0 + row) * (long)K + kb + c16 * 8;
        CP_ASYNC16(s, g);
    }
#pragma unroll
    for (int j = 0; j < 2; j++) {
        int idx = tid + j * 512;
        int c16 = idx & 3, row = (idx >> 2) & 127, arr = idx >> 9;
        uint32_t s = st + 20480 + arr * 10240 + row * ROWSTRIDE + c16 * 16;
        const __nv_bfloat16* g = (arr ? Blo : Bhi) + (bRow0 + row) * (long)K + kb + c16 * 8;
        CP_ASYNC16(s, g);
    }
}

__global__ __launch_bounds__(512, 1)
void gemm3_kernel(const __nv_bfloat16* __restrict__ Ahi,
                  const __nv_bfloat16* __restrict__ Alo,
                  const __nv_bfloat16* __restrict__ Bhi,
                  const __nv_bfloat16* __restrict__ Blo,
                  const int* __restrict__ langs,
                  float* __restrict__ outF)
{
    extern __shared__ char smem[];
    const uint32_t sbase = smem_to_u32(smem);

    const int tid = threadIdx.x;
    const int wid = tid >> 5;
    const int lane = tid & 31;
    const int wm = wid >> 2;   // 0..3
    const int wn = wid & 3;    // 0..3

    const int bz = blockIdx.z;
    const int m0 = blockIdx.y * 128;
    const int n0 = blockIdx.x * 128;

    const int lang = langs[bz];
    int e = lang - 4;
    if (e < 0) e = 0;
    if (e > 7) e = 7;
    const int cnt = (lang > 3) ? 1 : 0;
    const float rw = (cnt == 0) ? 1.0f : (1.0f / (float)cnt);

    const long aRow0 = (long)bz * S_ + m0;
    const long bRow0 = (long)e * D_ + n0;
    const int K = F_;
    const int NC = K / BK;     // 128

    float acc[2][4][4];
#pragma unroll
    for (int i = 0; i < 2; i++)
#pragma unroll
        for (int j = 0; j < 4; j++)
#pragma unroll
            for (int q = 0; q < 4; q++) acc[i][j][q] = 0.0f;

#pragma unroll
    for (int s = 0; s < STAGES - 1; s++) {
        load_stage_g3(sbase + s * STAGE_B, Ahi, Alo, Bhi, Blo, aRow0, bRow0, K, s * BK, tid);
        CP_COMMIT();
    }

    for (int c = 0; c < NC; ++c) {
        CP_WAIT2();
        __syncthreads();
        int cn = c + STAGES - 1;
        if (cn < NC)
            load_stage_g3(sbase + (cn % STAGES) * STAGE_B, Ahi, Alo, Bhi, Blo,
                          aRow0, bRow0, K, cn * BK, tid);
        CP_COMMIT();

        const uint32_t st = sbase + (c % STAGES) * STAGE_B;
#pragma unroll
        for (int ks = 0; ks < 2; ks++) {
            uint32_t ahi[2][4], alo[2][4];
#pragma unroll
            for (int mt = 0; mt < 2; mt++) {
                int row = wm * 32 + mt * 16 + (lane & 15);
                uint32_t off = (uint32_t)(row * ROWSTRIDE + ks * 32 + (lane >> 4) * 16);
                ldsm_x4(ahi[mt][0], ahi[mt][1], ahi[mt][2], ahi[mt][3], st + off);
                ldsm_x4(alo[mt][0], alo[mt][1], alo[mt][2], alo[mt][3], st + 10240 + off);
            }
            uint32_t bhi[4][2], blo[4][2];
#pragma unroll
            for (int bt = 0; bt < 2; bt++) {
                int row = wn * 32 + bt * 16 + (lane & 15);
                uint32_t off = (uint32_t)(row * ROWSTRIDE + ks * 32 + (lane >> 4) * 16);
                uint32_t r0, r1, r2, r3;
                ldsm_x4(r0, r1, r2, r3, st + 20480 + off);
                bhi[bt * 2][0] = r0; bhi[bt * 2][1] = r2;
                bhi[bt * 2 + 1][0] = r1; bhi[bt * 2 + 1][1] = r3;
                ldsm_x4(r0, r1, r2, r3, st + 30720 + off);
                blo[bt * 2][0] = r0; blo[bt * 2][1] = r2;
                blo[bt * 2 + 1][0] = r1; blo[bt * 2 + 1][1] = r3;
            }
#pragma unroll
            for (int mt = 0; mt < 2; mt++)
#pragma unroll
                for (int nt = 0; nt < 4; nt++) {
                    mma_16816(acc[mt][nt], ahi[mt], bhi[nt]);
                    mma_16816(acc[mt][nt], ahi[mt], blo[nt]);
                    mma_16816(acc[mt][nt], alo[mt], bhi[nt]);
                }
        }
        __syncthreads();
    }

    const int qr = lane >> 2;
    const int qc = (lane & 3) * 2;
#pragma unroll
    for (int mt = 0; mt < 2; mt++) {
#pragma unroll
        for (int half = 0; half < 2; half++) {
            const int gm = m0 + wm * 32 + mt * 16 + qr + half * 8;
            const long rowBase = ((long)bz * S_ + gm) * (long)D_;
#pragma unroll
            for (int nt = 0; nt < 4; nt++) {
                const int gn = n0 + wn * 32 + nt * 8 + qc;
                *(float2*)(outF + rowBase + gn) =
                    make_float2(acc[mt][nt][half * 2] * rw, acc[mt][nt][half * 2 + 1] * rw);
            }
        }
    }
}

// ---------------------------------------------------------------------------
// Launch
// ---------------------------------------------------------------------------
extern "C" void kernel_launch(void* const* d_in, const int* in_sizes, int n_in,
                              void* d_out, int out_size)
{
    const float* x     = (const float*)d_in[0];   // [B,S,D]
    const float* w1    = (const float*)d_in[1];   // [E,D,F]
    const float* w2    = (const float*)d_in[2];   // [E,F,D]
    const float* w3    = (const float*)d_in[3];   // [E,D,F]
    const int*   langs = (const int*)  d_in[4];   // [B,1]
    float* out = (float*)d_out;                   // [B,S,D]

    __nv_bfloat16 *xhi, *xlo, *w1hi, *w1lo, *w3hi, *w3lo, *w2hi, *w2lo, *hhi, *hlo;
    cudaGetSymbolAddress((void**)&xhi,  g_xhi);
    cudaGetSymbolAddress((void**)&xlo,  g_xlo);
    cudaGetSymbolAddress((void**)&w1hi, g_w1hi);
    cudaGetSymbolAddress((void**)&w1lo, g_w1lo);
    cudaGetSymbolAddress((void**)&w3hi, g_w3hi);
    cudaGetSymbolAddress((void**)&w3lo, g_w3lo);
    cudaGetSymbolAddress((void**)&w2hi, g_w2hi);
    cudaGetSymbolAddress((void**)&w2lo, g_w2lo);
    cudaGetSymbolAddress((void**)&hhi,  g_hhi);
    cudaGetSymbolAddress((void**)&hlo,  g_hlo);

    cudaFuncSetAttribute(fused_gemm12_kernel,
                         cudaFuncAttributeMaxDynamicSharedMemorySize, SMEM_TOTAL);
    cudaFuncSetAttribute(gemm3_kernel,
                         cudaFuncAttributeMaxDynamicSharedMemorySize, SMEM_TOTAL);

    // 1) split x -> bf16 hi/lo
    {
        long n4 = (long)B_ * S_ * D_ / 4;
        split_x_kernel<<<(unsigned)(n4 / 256), 256>>>(x, xhi, xlo, n4);
    }
    // 2) transpose + split weights
    {
        dim3 blk(32, 8);
        dim3 g1(F_ / 32, D_ / 32, E_);
        transpose_split_kernel<<<g1, blk>>>(w1, w1hi, w1lo, D_, F_);
        transpose_split_kernel<<<g1, blk>>>(w3, w3hi, w3lo, D_, F_);
        dim3 g2(D_ / 32, F_ / 32, E_);
        transpose_split_kernel<<<g2, blk>>>(w2, w2hi, w2lo, F_, D_);
    }
    // 3) fused GEMM1+GEMM2 + GLU -> h (bf16 hi/lo)
    {
        dim3 grid(F_ / 64, S_ / 128, B_);
        fused_gemm12_kernel<<<grid, 512, SMEM_TOTAL>>>(
            xhi, xlo, w1hi, w1lo, w3hi, w3lo, langs, hhi, hlo);
    }
    // 4) GEMM3: out = (h @ W2^T) * rw
    {
        dim3 grid(D_ / 128, S_ / 128, B_);
        gemm3_kernel<<<grid, 512, SMEM_TOTAL>>>(
            hhi, hlo, w2hi, w2lo, langs, out);
    }
}

// round 5
// speedup vs baseline: 2.7916x; 1.3253x over previous
#include <cuda_runtime.h>
#include <cuda_bf16.h>
#include <math.h>
#include <stdint.h>

// ---------------------------------------------------------------------------
// Problem constants
// ---------------------------------------------------------------------------
#define B_ 8
#define S_ 2048
#define D_ 1024
#define F_ 4096
#define E_ 8

// ---------------------------------------------------------------------------
// Scratch (__device__ globals).  Weights stay K-MAJOR (native layout).
// ---------------------------------------------------------------------------
__device__ __nv_bfloat16 g_xhi[(size_t)B_ * S_ * D_];
__device__ __nv_bfloat16 g_xlo[(size_t)B_ * S_ * D_];
__device__ __nv_bfloat16 g_w1hi[(size_t)E_ * D_ * F_];
__device__ __nv_bfloat16 g_w1lo[(size_t)E_ * D_ * F_];
__device__ __nv_bfloat16 g_w3hi[(size_t)E_ * D_ * F_];
__device__ __nv_bfloat16 g_w3lo[(size_t)E_ * D_ * F_];
__device__ __nv_bfloat16 g_w2hi[(size_t)E_ * F_ * D_];
__device__ __nv_bfloat16 g_w2lo[(size_t)E_ * F_ * D_];
__device__ __nv_bfloat16 g_hhi[(size_t)B_ * S_ * F_];
__device__ __nv_bfloat16 g_hlo[(size_t)B_ * S_ * F_];

// ---------------------------------------------------------------------------
// PTX helpers (base-target-safe)
// ---------------------------------------------------------------------------
__device__ __forceinline__ uint32_t smem_to_u32(const void* p) {
    uint32_t a;
    asm("{ .reg .u64 t; cvta.to.shared.u64 t, %1; cvt.u32.u64 %0, t; }" : "=r"(a) : "l"(p));
    return a;
}

#define CP_ASYNC16(saddr, gptr) \
    asm volatile("cp.async.cg.shared.global [%0], [%1], 16;" :: "r"(saddr), "l"(gptr))
#define CP_COMMIT()  asm volatile("cp.async.commit_group;" ::: "memory")
#define CP_WAIT1()   asm volatile("cp.async.wait_group 1;" ::: "memory")
#define CP_WAIT0()   asm volatile("cp.async.wait_group 0;" ::: "memory")

__device__ __forceinline__ void ldsm_x4(uint32_t& r0, uint32_t& r1, uint32_t& r2,
                                        uint32_t& r3, uint32_t addr) {
    asm volatile("ldmatrix.sync.aligned.m8n8.x4.shared.b16 {%0,%1,%2,%3}, [%4];"
                 : "=r"(r0), "=r"(r1), "=r"(r2), "=r"(r3) : "r"(addr));
}
__device__ __forceinline__ void ldsm_x4_t(uint32_t& r0, uint32_t& r1, uint32_t& r2,
                                          uint32_t& r3, uint32_t addr) {
    asm volatile("ldmatrix.sync.aligned.m8n8.x4.trans.shared.b16 {%0,%1,%2,%3}, [%4];"
                 : "=r"(r0), "=r"(r1), "=r"(r2), "=r"(r3) : "r"(addr));
}

__device__ __forceinline__ void mma_16816(float* d, const uint32_t* a, const uint32_t* b) {
    asm volatile(
        "mma.sync.aligned.m16n8k16.row.col.f32.bf16.bf16.f32 "
        "{%0,%1,%2,%3}, {%4,%5,%6,%7}, {%8,%9}, {%0,%1,%2,%3};"
        : "+f"(d[0]), "+f"(d[1]), "+f"(d[2]), "+f"(d[3])
        : "r"(a[0]), "r"(a[1]), "r"(a[2]), "r"(a[3]), "r"(b[0]), "r"(b[1]));
}

// ---------------------------------------------------------------------------
// Prep: elementwise fp32 -> bf16 hi/lo split (used for x, w1, w3, w2)
// ---------------------------------------------------------------------------
__global__ __launch_bounds__(256)
void split_kernel(const float* __restrict__ src,
                  __nv_bfloat16* __restrict__ hi,
                  __nv_bfloat16* __restrict__ lo, long n4)
{
    long i = (long)blockIdx.x * blockDim.x + threadIdx.x;
    if (i >= n4) return;
    float4 v = ((const float4*)src)[i];
    union { uint2 u; __nv_bfloat16 h[4]; } ph, pl;
    float vv[4] = {v.x, v.y, v.z, v.w};
#pragma unroll
    for (int j = 0; j < 4; j++) {
        __nv_bfloat16 h = __float2bfloat16(vv[j]);
        ph.h[j] = h;
        pl.h[j] = __float2bfloat16(vv[j] - __bfloat162float(h));
    }
    ((uint2*)hi)[i] = ph.u;
    ((uint2*)lo)[i] = pl.u;
}

// ---------------------------------------------------------------------------
// Layout constants
// ---------------------------------------------------------------------------
#define BK 32
#define A_STRIDE 80          // A rows: 64B data + 16B pad
#define A_ARR 10240          // 128 * 80
// fused B (w1/w3): [32 k][64 n] rows of 128B, stride 144
#define FB_STRIDE 144
#define FB_ARR 4608          // 32 * 144
#define F_STAGE (2*A_ARR + 4*FB_ARR)     // 38912
#define F_SMEM  (2 * F_STAGE)            // 77824
// gemm3 B (w2): [32 k][128 n] rows of 256B, stride 272
#define GB_STRIDE 272
#define GB_ARR 8704          // 32 * 272
#define G_STAGE (2*A_ARR + 2*GB_ARR)     // 37888
#define G_SMEM  (2 * G_STAGE)            // 75776

// ===========================================================================
// FUSED: a = x@W1, b = x@W3 (both [m][k] x [k][n]); h = gelu(a)*b -> bf16 hi/lo
// CTA 128m x 64n x 2 outputs, 8 warps: out_sel = wid>>2; w4: wm=w4>>1, wn=w4&1.
// Warp tile 64x32.  2 CTAs/SM.
// ===========================================================================
__device__ __forceinline__ void f_load_stage(
    uint32_t st,
    const __nv_bfloat16* __restrict__ Ahi, const __nv_bfloat16* __restrict__ Alo,
    const __nv_bfloat16* __restrict__ B1hi, const __nv_bfloat16* __restrict__ B1lo,
    const __nv_bfloat16* __restrict__ B3hi, const __nv_bfloat16* __restrict__ B3lo,
    long aRow0, long wBase, int n0, int kb, int tid)
{
    // A: 1024 ops (2 arrays x 128 rows x 4 chunks)
#pragma unroll
    for (int j = 0; j < 4; j++) {
        int i = tid + j * 256;
        int arr = i >> 9, row = (i >> 2) & 127, c16 = i & 3;
        uint32_t s = st + arr * A_ARR + row * A_STRIDE + c16 * 16;
        const __nv_bfloat16* g = (arr ? Alo : Ahi) + (aRow0 + row) * (long)D_ + kb + c16 * 8;
        CP_ASYNC16(s, g);
    }
    // B: 1024 ops (4 arrays x 32 rows x 8 chunks of 16B over 64 n-cols)
#pragma unroll
    for (int j = 0; j < 4; j++) {
        int i = tid + j * 256;
        int arr = i >> 8, row = (i >> 3) & 31, c16 = i & 7;
        uint32_t s = st + 2 * A_ARR + arr * FB_ARR + row * FB_STRIDE + c16 * 16;
        const __nv_bfloat16* g;
        if (arr == 0) g = B1hi; else if (arr == 1) g = B1lo;
        else if (arr == 2) g = B3hi; else g = B3lo;
        g += wBase + (long)(kb + row) * F_ + n0 + c16 * 8;
        CP_ASYNC16(s, g);
    }
}

__global__ __launch_bounds__(256, 2)
void fused_gemm12_kernel(const __nv_bfloat16* __restrict__ Ahi,
                         const __nv_bfloat16* __restrict__ Alo,
                         const __nv_bfloat16* __restrict__ B1hi,
                         const __nv_bfloat16* __restrict__ B1lo,
                         const __nv_bfloat16* __restrict__ B3hi,
                         const __nv_bfloat16* __restrict__ B3lo,
                         const int* __restrict__ langs,
                         __nv_bfloat16* __restrict__ outHi,
                         __nv_bfloat16* __restrict__ outLo)
{
    extern __shared__ char smem[];
    const uint32_t sbase = smem_to_u32(smem);

    const int tid = threadIdx.x;
    const int wid = tid >> 5;
    const int lane = tid & 31;
    const int out_sel = wid >> 2;
    const int w4 = wid & 3;
    const int wm = w4 >> 1;
    const int wn = w4 & 1;

    const int bz = blockIdx.z;
    const int m0 = blockIdx.y * 128;
    const int n0 = blockIdx.x * 64;

    const int lang = langs[bz];
    int e = lang - 4; if (e < 0) e = 0; if (e > 7) e = 7;

    const long aRow0 = (long)bz * S_ + m0;
    const long wBase = (long)e * D_ * F_;
    const int NC = D_ / BK;    // 32

    float acc[4][4][4];
#pragma unroll
    for (int i = 0; i < 4; i++)
#pragma unroll
        for (int j = 0; j < 4; j++)
#pragma unroll
            for (int q = 0; q < 4; q++) acc[i][j][q] = 0.0f;

    f_load_stage(sbase, Ahi, Alo, B1hi, B1lo, B3hi, B3lo, aRow0, wBase, n0, 0, tid);
    CP_COMMIT();

    const uint32_t stBoff = 2 * A_ARR + out_sel * (2 * FB_ARR);

    for (int c = 0; c < NC; ++c) {
        if (c + 1 < NC) {
            f_load_stage(sbase + ((c + 1) & 1) * F_STAGE, Ahi, Alo, B1hi, B1lo, B3hi, B3lo,
                         aRow0, wBase, n0, (c + 1) * BK, tid);
            CP_COMMIT();
            CP_WAIT1();
        } else {
            CP_WAIT0();
        }
        __syncthreads();

        const uint32_t st = sbase + (c & 1) * F_STAGE;
        const uint32_t stB = st + stBoff;
#pragma unroll
        for (int ks = 0; ks < 2; ks++) {
            uint32_t bhi[4][2], blo[4][2];
#pragma unroll
            for (int half = 0; half < 2; half++) {
                uint32_t addr = stB + (ks * 16 + (lane & 15)) * FB_STRIDE
                                + wn * 64 + half * 32 + (lane >> 4) * 16;
                uint32_t r0, r1, r2, r3;
                ldsm_x4_t(r0, r1, r2, r3, addr);
                bhi[half * 2][0] = r0; bhi[half * 2][1] = r1;
                bhi[half * 2 + 1][0] = r2; bhi[half * 2 + 1][1] = r3;
                ldsm_x4_t(r0, r1, r2, r3, addr + FB_ARR);
                blo[half * 2][0] = r0; blo[half * 2][1] = r1;
                blo[half * 2 + 1][0] = r2; blo[half * 2 + 1][1] = r3;
            }
#pragma unroll
            for (int mt = 0; mt < 4; mt++) {
                int row = wm * 64 + mt * 16 + (lane & 15);
                uint32_t off = (uint32_t)(row * A_STRIDE + ks * 32 + (lane >> 4) * 16);
                uint32_t ah[4], al[4];
                ldsm_x4(ah[0], ah[1], ah[2], ah[3], st + off);
                ldsm_x4(al[0], al[1], al[2], al[3], st + A_ARR + off);
#pragma unroll
                for (int nt = 0; nt < 4; nt++) {
                    mma_16816(acc[mt][nt], ah, bhi[nt]);
                    mma_16816(acc[mt][nt], ah, blo[nt]);
                    mma_16816(acc[mt][nt], al, bhi[nt]);
                }
            }
        }
        __syncthreads();
    }

    // --- epilogue: a-warps dump acc to smem; b-warps apply gelu(a)*b ---
    float* ex = (float*)smem;     // 4 warps x 2048 floats = 32 KB (stage0, now free)
    if (out_sel == 0) {
#pragma unroll
        for (int mt = 0; mt < 4; mt++)
#pragma unroll
            for (int nt = 0; nt < 4; nt++)
#pragma unroll
                for (int q = 0; q < 4; q++) {
                    int i = (mt * 4 + nt) * 4 + q;
                    ex[w4 * 2048 + i * 32 + lane] = acc[mt][nt][q];
                }
    }
    __syncthreads();
    if (out_sel == 1) {
        const int qr = lane >> 2;
        const int qc = (lane & 3) * 2;
#pragma unroll
        for (int mt = 0; mt < 4; mt++) {
#pragma unroll
            for (int half = 0; half < 2; half++) {
                const int gm = m0 + wm * 64 + mt * 16 + qr + half * 8;
                const long rowBase = ((long)bz * S_ + gm) * (long)F_;
#pragma unroll
                for (int nt = 0; nt < 4; nt++) {
                    const int gn = n0 + wn * 32 + nt * 8 + qc;
                    const long idx = rowBase + gn;
                    float b0 = acc[mt][nt][half * 2 + 0];
                    float b1 = acc[mt][nt][half * 2 + 1];
                    int i0 = (mt * 4 + nt) * 4 + half * 2;
                    float a0 = ex[w4 * 2048 + i0 * 32 + lane];
                    float a1 = ex[w4 * 2048 + (i0 + 1) * 32 + lane];
                    float g0 = 0.5f * a0 * (1.0f + erff(a0 * 0.70710678118654752f));
                    float g1 = 0.5f * a1 * (1.0f + erff(a1 * 0.70710678118654752f));
                    float h0 = g0 * b0, h1 = g1 * b1;
                    __nv_bfloat16 x0 = __float2bfloat16(h0);
                    __nv_bfloat16 x1 = __float2bfloat16(h1);
                    __nv_bfloat16 l0 = __float2bfloat16(h0 - __bfloat162float(x0));
                    __nv_bfloat16 l1 = __float2bfloat16(h1 - __bfloat162float(x1));
                    union { uint32_t u; __nv_bfloat16 h[2]; } uh, ul;
                    uh.h[0] = x0; uh.h[1] = x1;
                    ul.h[0] = l0; ul.h[1] = l1;
                    *(uint32_t*)(outHi + idx) = uh.u;
                    *(uint32_t*)(outLo + idx) = ul.u;
                }
            }
        }
    }
}

// ===========================================================================
// GEMM3: out = (h @ W2) * rw.   CTA 128m x 128n, 8 warps 2m x 4n of 64x32.
// ===========================================================================
__device__ __forceinline__ void g_load_stage(
    uint32_t st,
    const __nv_bfloat16* __restrict__ Ahi, const __nv_bfloat16* __restrict__ Alo,
    const __nv_bfloat16* __restrict__ Bhi, const __nv_bfloat16* __restrict__ Blo,
    long aRow0, long wBase, int n0, int kb, int tid)
{
#pragma unroll
    for (int j = 0; j < 4; j++) {
        int i = tid + j * 256;
        int arr = i >> 9, row = (i >> 2) & 127, c16 = i & 3;
        uint32_t s = st + arr * A_ARR + row * A_STRIDE + c16 * 16;
        const __nv_bfloat16* g = (arr ? Alo : Ahi) + (aRow0 + row) * (long)F_ + kb + c16 * 8;
        CP_ASYNC16(s, g);
    }
    // B: 2 arrays x 32 rows x 16 chunks over 128 n-cols
#pragma unroll
    for (int j = 0; j < 4; j++) {
        int i = tid + j * 256;
        int arr = i >> 9, row = (i >> 4) & 31, c16 = i & 15;
        uint32_t s = st + 2 * A_ARR + arr * GB_ARR + row * GB_STRIDE + c16 * 16;
        const __nv_bfloat16* g = (arr ? Blo : Bhi)
            + wBase + (long)(kb + row) * D_ + n0 + c16 * 8;
        CP_ASYNC16(s, g);
    }
}

__global__ __launch_bounds__(256, 2)
void gemm3_kernel(const __nv_bfloat16* __restrict__ Ahi,
                  const __nv_bfloat16* __restrict__ Alo,
                  const __nv_bfloat16* __restrict__ Bhi,
                  const __nv_bfloat16* __restrict__ Blo,
                  const int* __restrict__ langs,
                  float* __restrict__ outF)
{
    extern __shared__ char smem[];
    const uint32_t sbase = smem_to_u32(smem);

    const int tid = threadIdx.x;
    const int wid = tid >> 5;
    const int lane = tid & 31;
    const int wm = wid >> 2;     // 0..1
    const int wn = wid & 3;      // 0..3

    const int bz = blockIdx.z;
    const int m0 = blockIdx.y * 128;
    const int n0 = blockIdx.x * 128;

    const int lang = langs[bz];
    int e = lang - 4; if (e < 0) e = 0; if (e > 7) e = 7;
    const int cnt = (lang > 3) ? 1 : 0;
    const float rw = (cnt == 0) ? 1.0f : (1.0f / (float)cnt);

    const long aRow0 = (long)bz * S_ + m0;
    const long wBase = (long)e * F_ * D_;
    const int NC = F_ / BK;      // 128

    float acc[4][4][4];
#pragma unroll
    for (int i = 0; i < 4; i++)
#pragma unroll
        for (int j = 0; j < 4; j++)
#pragma unroll
            for (int q = 0; q < 4; q++) acc[i][j][q] = 0.0f;

    g_load_stage(sbase, Ahi, Alo, Bhi, Blo, aRow0, wBase, n0, 0, tid);
    CP_COMMIT();

    for (int c = 0; c < NC; ++c) {
        if (c + 1 < NC) {
            g_load_stage(sbase + ((c + 1) & 1) * G_STAGE, Ahi, Alo, Bhi, Blo,
                         aRow0, wBase, n0, (c + 1) * BK, tid);
            CP_COMMIT();
            CP_WAIT1();
        } else {
            CP_WAIT0();
        }
        __syncthreads();

        const uint32_t st = sbase + (c & 1) * G_STAGE;
        const uint32_t stB = st + 2 * A_ARR;
#pragma unroll
        for (int ks = 0; ks < 2; ks++) {
            uint32_t bhi[4][2], blo[4][2];
#pragma unroll
            for (int half = 0; half < 2; half++) {
                uint32_t addr = stB + (ks * 16 + (lane & 15)) * GB_STRIDE
                                + wn * 64 + half * 32 + (lane >> 4) * 16;
                uint32_t r0, r1, r2, r3;
                ldsm_x4_t(r0, r1, r2, r3, addr);
                bhi[half * 2][0] = r0; bhi[half * 2][1] = r1;
                bhi[half * 2 + 1][0] = r2; bhi[half * 2 + 1][1] = r3;
                ldsm_x4_t(r0, r1, r2, r3, addr + GB_ARR);
                blo[half * 2][0] = r0; blo[half * 2][1] = r1;
                blo[half * 2 + 1][0] = r2; blo[half * 2 + 1][1] = r3;
            }
#pragma unroll
            for (int mt = 0; mt < 4; mt++) {
                int row = wm * 64 + mt * 16 + (lane & 15);
                uint32_t off = (uint32_t)(row * A_STRIDE + ks * 32 + (lane >> 4) * 16);
                uint32_t ah[4], al[4];
                ldsm_x4(ah[0], ah[1], ah[2], ah[3], st + off);
                ldsm_x4(al[0], al[1], al[2], al[3], st + A_ARR + off);
#pragma unroll
                for (int nt = 0; nt < 4; nt++) {
                    mma_16816(acc[mt][nt], ah, bhi[nt]);
                    mma_16816(acc[mt][nt], ah, blo[nt]);
                    mma_16816(acc[mt][nt], al, bhi[nt]);
                }
            }
        }
        __syncthreads();
    }

    const int qr = lane >> 2;
    const int qc = (lane & 3) * 2;
#pragma unroll
    for (int mt = 0; mt < 4; mt++) {
#pragma unroll
        for (int half = 0; half < 2; half++) {
            const int gm = m0 + wm * 64 + mt * 16 + qr + half * 8;
            const long rowBase = ((long)bz * S_ + gm) * (long)D_;
#pragma unroll
            for (int nt = 0; nt < 4; nt++) {
                const int gn = n0 + wn * 32 + nt * 8 + qc;
                *(float2*)(outF + rowBase + gn) =
                    make_float2(acc[mt][nt][half * 2] * rw, acc[mt][nt][half * 2 + 1] * rw);
            }
        }
    }
}

// ---------------------------------------------------------------------------
// Launch
// ---------------------------------------------------------------------------
extern "C" void kernel_launch(void* const* d_in, const int* in_sizes, int n_in,
                              void* d_out, int out_size)
{
    const float* x     = (const float*)d_in[0];   // [B,S,D]
    const float* w1    = (const float*)d_in[1];   // [E,D,F]
    const float* w2    = (const float*)d_in[2];   // [E,F,D]
    const float* w3    = (const float*)d_in[3];   // [E,D,F]
    const int*   langs = (const int*)  d_in[4];   // [B,1]
    float* out = (float*)d_out;                   // [B,S,D]

    __nv_bfloat16 *xhi, *xlo, *w1hi, *w1lo, *w3hi, *w3lo, *w2hi, *w2lo, *hhi, *hlo;
    cudaGetSymbolAddress((void**)&xhi,  g_xhi);
    cudaGetSymbolAddress((void**)&xlo,  g_xlo);
    cudaGetSymbolAddress((void**)&w1hi, g_w1hi);
    cudaGetSymbolAddress((void**)&w1lo, g_w1lo);
    cudaGetSymbolAddress((void**)&w3hi, g_w3hi);
    cudaGetSymbolAddress((void**)&w3lo, g_w3lo);
    cudaGetSymbolAddress((void**)&w2hi, g_w2hi);
    cudaGetSymbolAddress((void**)&w2lo, g_w2lo);
    cudaGetSymbolAddress((void**)&hhi,  g_hhi);
    cudaGetSymbolAddress((void**)&hlo,  g_hlo);

    cudaFuncSetAttribute(fused_gemm12_kernel,
                         cudaFuncAttributeMaxDynamicSharedMemorySize, F_SMEM);
    cudaFuncSetAttribute(gemm3_kernel,
                         cudaFuncAttributeMaxDynamicSharedMemorySize, G_SMEM);

    // 1) splits (x, w1, w3, w2) — all elementwise, K-major preserved
    {
        long nx = (long)B_ * S_ * D_ / 4;
        split_kernel<<<(unsigned)(nx / 256), 256>>>(x, xhi, xlo, nx);
        long nw = (long)E_ * D_ * F_ / 4;
        split_kernel<<<(unsigned)(nw / 256), 256>>>(w1, w1hi, w1lo, nw);
        split_kernel<<<(unsigned)(nw / 256), 256>>>(w3, w3hi, w3lo, nw);
        split_kernel<<<(unsigned)(nw / 256), 256>>>(w2, w2hi, w2lo, nw);
    }
    // 2) fused GEMM1+GEMM2 + GLU -> h (bf16 hi/lo)
    {
        dim3 grid(F_ / 64, S_ / 128, B_);
        fused_gemm12_kernel<<<grid, 256, F_SMEM>>>(
            xhi, xlo, w1hi, w1lo, w3hi, w3lo, langs, hhi, hlo);
    }
    // 3) GEMM3: out = (h @ W2) * rw
    {
        dim3 grid(D_ / 128, S_ / 128, B_);
        gemm3_kernel<<<grid, 256, G_SMEM>>>(
            hhi, hlo, w2hi, w2lo, langs, out);
    }
}

// round 6
// speedup vs baseline: 3.2238x; 1.1548x over previous
#include <cuda_runtime.h>
#include <cuda_bf16.h>
#include <math.h>
#include <stdint.h>

// ---------------------------------------------------------------------------
#define B_ 8
#define S_ 2048
#define D_ 1024
#define F_ 4096
#define E_ 8

// ---------------------------------------------------------------------------
// Scratch (__device__ globals). Weights stay K-major.
// ---------------------------------------------------------------------------
__device__ __nv_bfloat16 g_xhi[(size_t)B_ * S_ * D_];
__device__ __nv_bfloat16 g_xlo[(size_t)B_ * S_ * D_];
__device__ __nv_bfloat16 g_w1hi[(size_t)E_ * D_ * F_];
__device__ __nv_bfloat16 g_w1lo[(size_t)E_ * D_ * F_];
__device__ __nv_bfloat16 g_w3hi[(size_t)E_ * D_ * F_];
__device__ __nv_bfloat16 g_w3lo[(size_t)E_ * D_ * F_];
__device__ __nv_bfloat16 g_w2hi[(size_t)E_ * F_ * D_];
__device__ __nv_bfloat16 g_w2lo[(size_t)E_ * F_ * D_];
__device__ __nv_bfloat16 g_hhi[(size_t)B_ * S_ * F_];
__device__ __nv_bfloat16 g_hlo[(size_t)B_ * S_ * F_];
__device__ int           g_used[E_];

// ---------------------------------------------------------------------------
// PTX helpers (base-target-safe)
// ---------------------------------------------------------------------------
__device__ __forceinline__ uint32_t smem_to_u32(const void* p) {
    uint32_t a;
    asm("{ .reg .u64 t; cvta.to.shared.u64 t, %1; cvt.u32.u64 %0, t; }" : "=r"(a) : "l"(p));
    return a;
}
#define CP_ASYNC16(saddr, gptr) \
    asm volatile("cp.async.cg.shared.global [%0], [%1], 16;" :: "r"(saddr), "l"(gptr))
#define CP_COMMIT()  asm volatile("cp.async.commit_group;" ::: "memory")
#define CP_WAIT1()   asm volatile("cp.async.wait_group 1;" ::: "memory")

__device__ __forceinline__ void ldsm_x4(uint32_t& r0, uint32_t& r1, uint32_t& r2,
                                        uint32_t& r3, uint32_t addr) {
    asm volatile("ldmatrix.sync.aligned.m8n8.x4.shared.b16 {%0,%1,%2,%3}, [%4];"
                 : "=r"(r0), "=r"(r1), "=r"(r2), "=r"(r3) : "r"(addr));
}
__device__ __forceinline__ void ldsm_x4_t(uint32_t& r0, uint32_t& r1, uint32_t& r2,
                                          uint32_t& r3, uint32_t addr) {
    asm volatile("ldmatrix.sync.aligned.m8n8.x4.trans.shared.b16 {%0,%1,%2,%3}, [%4];"
                 : "=r"(r0), "=r"(r1), "=r"(r2), "=r"(r3) : "r"(addr));
}
__device__ __forceinline__ void mma_16816(float* d, const uint32_t* a, const uint32_t* b) {
    asm volatile(
        "mma.sync.aligned.m16n8k16.row.col.f32.bf16.bf16.f32 "
        "{%0,%1,%2,%3}, {%4,%5,%6,%7}, {%8,%9}, {%0,%1,%2,%3};"
        : "+f"(d[0]), "+f"(d[1]), "+f"(d[2]), "+f"(d[3])
        : "r"(a[0]), "r"(a[1]), "r"(a[2]), "r"(a[3]), "r"(b[0]), "r"(b[1]));
}

// ---------------------------------------------------------------------------
// Prep kernels
// ---------------------------------------------------------------------------
__global__ void mask_kernel(const int* __restrict__ langs) {
    int t = threadIdx.x;
    if (t < E_) {
        int used = 0;
#pragma unroll
        for (int b = 0; b < B_; b++)
            if (langs[b] - 4 == t) used = 1;
        g_used[t] = used;
    }
}

__global__ __launch_bounds__(256)
void split_kernel(const float* __restrict__ src,
                  __nv_bfloat16* __restrict__ hi,
                  __nv_bfloat16* __restrict__ lo, long n4)
{
    long i = (long)blockIdx.x * blockDim.x + threadIdx.x;
    if (i >= n4) return;
    float4 v = ((const float4*)src)[i];
    union { uint2 u; __nv_bfloat16 h[4]; } ph, pl;
    float vv[4] = {v.x, v.y, v.z, v.w};
#pragma unroll
    for (int j = 0; j < 4; j++) {
        __nv_bfloat16 h = __float2bfloat16(vv[j]);
        ph.h[j] = h;
        pl.h[j] = __float2bfloat16(vv[j] - __bfloat162float(h));
    }
    ((uint2*)hi)[i] = ph.u;
    ((uint2*)lo)[i] = pl.u;
}

// weight split, gated by g_used[blockIdx.z]
__global__ __launch_bounds__(256)
void split_w_kernel(const float* __restrict__ src,
                    __nv_bfloat16* __restrict__ hi,
                    __nv_bfloat16* __restrict__ lo)
{
    const int e = blockIdx.z;
    if (!g_used[e]) return;
    const long per = (long)D_ * F_ / 4;          // float4 per expert
    long i = e * per + (long)blockIdx.x * blockDim.x + threadIdx.x;
    float4 v = ((const float4*)src)[i];
    union { uint2 u; __nv_bfloat16 h[4]; } ph, pl;
    float vv[4] = {v.x, v.y, v.z, v.w};
#pragma unroll
    for (int j = 0; j < 4; j++) {
        __nv_bfloat16 h = __float2bfloat16(vv[j]);
        ph.h[j] = h;
        pl.h[j] = __float2bfloat16(vv[j] - __bfloat162float(h));
    }
    ((uint2*)hi)[i] = ph.u;
    ((uint2*)lo)[i] = pl.u;
}

// ---------------------------------------------------------------------------
// Layout constants (swizzled, no padding)
// ---------------------------------------------------------------------------
#define BK 32
#define A_ARR 8192                  // 128 rows x 64B (swizzled)
#define FB_ARR 4096                 // 32 rows x 128B (swizzled)
#define F_STAGE (2*A_ARR + 4*FB_ARR)   // 32768
#define F_SMEM  (3 * F_STAGE)          // 98304
#define GB_ARR 8192                 // 32 rows x 256B (swizzled)
#define G_STAGE (2*A_ARR + 2*GB_ARR)   // 32768
#define G_SMEM  (3 * G_STAGE)          // 98304

// swizzle: A rows 64B wide, chunk q in 0..3:  q' = q ^ ((row>>1)&3)
__device__ __forceinline__ uint32_t a_off(int row, int q) {
    return (uint32_t)(row * 64 + ((q ^ ((row >> 1) & 3)) << 4));
}
// B rows 128B wide, chunk c in 0..7:  c' = c ^ (row&7)
__device__ __forceinline__ uint32_t fb_off(int row, int c) {
    return (uint32_t)(row * 128 + ((c ^ (row & 7)) << 4));
}
// B rows 256B wide, chunk c in 0..15: c' = c ^ (row&7)
__device__ __forceinline__ uint32_t gb_off(int row, int c) {
    return (uint32_t)(row * 256 + ((c ^ (row & 7)) << 4));
}

// ===========================================================================
// FUSED: a = x@W1, b = x@W3; h = gelu(a)*b -> bf16 hi/lo
// CTA 128m x 64n x 2 outputs, 8 warps: out_sel=wid>>2; wm=(wid&3)>>1, wn=wid&1.
// 3-stage, one __syncthreads per chunk, 2 CTAs/SM.
// ===========================================================================
__device__ __forceinline__ void f_load_stage(
    uint32_t st,
    const __nv_bfloat16* __restrict__ Ahi, const __nv_bfloat16* __restrict__ Alo,
    const __nv_bfloat16* __restrict__ B1hi, const __nv_bfloat16* __restrict__ B1lo,
    const __nv_bfloat16* __restrict__ B3hi, const __nv_bfloat16* __restrict__ B3lo,
    long aRow0, long wBase, int n0, int kb, int tid)
{
#pragma unroll
    for (int j = 0; j < 4; j++) {        // A: 2 arrays x 128 rows x 4 chunks
        int i = tid + j * 256;
        int arr = i >> 9, row = (i >> 2) & 127, c16 = i & 3;
        uint32_t s = st + arr * A_ARR + a_off(row, c16);
        const __nv_bfloat16* g = (arr ? Alo : Ahi) + (aRow0 + row) * (long)D_ + kb + c16 * 8;
        CP_ASYNC16(s, g);
    }
#pragma unroll
    for (int j = 0; j < 4; j++) {        // B: 4 arrays x 32 rows x 8 chunks
        int i = tid + j * 256;
        int arr = i >> 8, row = (i >> 3) & 31, c16 = i & 7;
        uint32_t s = st + 2 * A_ARR + arr * FB_ARR + fb_off(row, c16);
        const __nv_bfloat16* g;
        if (arr == 0) g = B1hi; else if (arr == 1) g = B1lo;
        else if (arr == 2) g = B3hi; else g = B3lo;
        g += wBase + (long)(kb + row) * F_ + n0 + c16 * 8;
        CP_ASYNC16(s, g);
    }
}

__global__ __launch_bounds__(256, 2)
void fused_gemm12_kernel(const __nv_bfloat16* __restrict__ Ahi,
                         const __nv_bfloat16* __restrict__ Alo,
                         const __nv_bfloat16* __restrict__ B1hi,
                         const __nv_bfloat16* __restrict__ B1lo,
                         const __nv_bfloat16* __restrict__ B3hi,
                         const __nv_bfloat16* __restrict__ B3lo,
                         const int* __restrict__ langs,
                         __nv_bfloat16* __restrict__ outHi,
                         __nv_bfloat16* __restrict__ outLo)
{
    extern __shared__ char smem[];
    const uint32_t sbase = smem_to_u32(smem);

    const int tid = threadIdx.x;
    const int wid = tid >> 5;
    const int lane = tid & 31;
    const int out_sel = wid >> 2;
    const int w4 = wid & 3;
    const int wm = w4 >> 1;
    const int wn = w4 & 1;

    const int bz = blockIdx.z;
    const int m0 = blockIdx.y * 128;
    const int n0 = blockIdx.x * 64;

    const int lang = langs[bz];
    int e = lang - 4; if (e < 0) e = 0; if (e > 7) e = 7;

    const long aRow0 = (long)bz * S_ + m0;
    const long wBase = (long)e * D_ * F_;
    const int NC = D_ / BK;    // 32

    float acc[4][4][4];
#pragma unroll
    for (int i = 0; i < 4; i++)
#pragma unroll
        for (int j = 0; j < 4; j++)
#pragma unroll
            for (int q = 0; q < 4; q++) acc[i][j][q] = 0.0f;

    f_load_stage(sbase, Ahi, Alo, B1hi, B1lo, B3hi, B3lo, aRow0, wBase, n0, 0, tid);
    CP_COMMIT();
    f_load_stage(sbase + F_STAGE, Ahi, Alo, B1hi, B1lo, B3hi, B3lo, aRow0, wBase, n0, BK, tid);
    CP_COMMIT();

    const uint32_t stBoff = 2 * A_ARR + out_sel * (2 * FB_ARR);
    int sIdx = 0;              // stage of chunk c
    int sNext = 2;             // stage for chunk c+2

    for (int c = 0; c < NC; ++c) {
        CP_WAIT1();            // chunk c data resident
        __syncthreads();       // visibility + all warps done with chunk c-1
        if (c + 2 < NC)
            f_load_stage(sbase + sNext * F_STAGE, Ahi, Alo, B1hi, B1lo, B3hi, B3lo,
                         aRow0, wBase, n0, (c + 2) * BK, tid);
        CP_COMMIT();

        const uint32_t st = sbase + sIdx * F_STAGE;
        const uint32_t stB = st + stBoff;
#pragma unroll
        for (int ks = 0; ks < 2; ks++) {
            uint32_t bhi[4][2], blo[4][2];
#pragma unroll
            for (int half = 0; half < 2; half++) {
                int brow = ks * 16 + (lane & 15);
                int bc = wn * 4 + half * 2 + (lane >> 4);
                uint32_t addr = stB + fb_off(brow, bc);
                uint32_t r0, r1, r2, r3;
                ldsm_x4_t(r0, r1, r2, r3, addr);
                bhi[half * 2][0] = r0; bhi[half * 2][1] = r1;
                bhi[half * 2 + 1][0] = r2; bhi[half * 2 + 1][1] = r3;
                ldsm_x4_t(r0, r1, r2, r3, addr + FB_ARR);
                blo[half * 2][0] = r0; blo[half * 2][1] = r1;
                blo[half * 2 + 1][0] = r2; blo[half * 2 + 1][1] = r3;
            }
#pragma unroll
            for (int mt = 0; mt < 4; mt++) {
                int row = wm * 64 + mt * 16 + (lane & 15);
                uint32_t off = a_off(row, ks * 2 + (lane >> 4));
                uint32_t ah[4], al[4];
                ldsm_x4(ah[0], ah[1], ah[2], ah[3], st + off);
                ldsm_x4(al[0], al[1], al[2], al[3], st + A_ARR + off);
#pragma unroll
                for (int nt = 0; nt < 4; nt++) {
                    mma_16816(acc[mt][nt], ah, bhi[nt]);
                    mma_16816(acc[mt][nt], ah, blo[nt]);
                    mma_16816(acc[mt][nt], al, bhi[nt]);
                }
            }
        }
        sIdx = (sIdx == 2) ? 0 : sIdx + 1;
        sNext = (sNext == 2) ? 0 : sNext + 1;
    }

    // --- epilogue: a-warps dump acc into stage-0 smem; b-warps apply gelu(a)*b ---
    __syncthreads();           // all warps done computing last chunk
    float* ex = (float*)smem;  // 32 KB (stage 0, free now)
    if (out_sel == 0) {
#pragma unroll
        for (int mt = 0; mt < 4; mt++)
#pragma unroll
            for (int nt = 0; nt < 4; nt++)
#pragma unroll
                for (int q = 0; q < 4; q++) {
                    int i = (mt * 4 + nt) * 4 + q;
                    ex[w4 * 2048 + i * 32 + lane] = acc[mt][nt][q];
                }
    }
    __syncthreads();
    if (out_sel == 1) {
        const int qr = lane >> 2;
        const int qc = (lane & 3) * 2;
#pragma unroll
        for (int mt = 0; mt < 4; mt++) {
#pragma unroll
            for (int half = 0; half < 2; half++) {
                const int gm = m0 + wm * 64 + mt * 16 + qr + half * 8;
                const long rowBase = ((long)bz * S_ + gm) * (long)F_;
#pragma unroll
                for (int nt = 0; nt < 4; nt++) {
                    const int gn = n0 + wn * 32 + nt * 8 + qc;
                    const long idx = rowBase + gn;
                    float b0 = acc[mt][nt][half * 2 + 0];
                    float b1 = acc[mt][nt][half * 2 + 1];
                    int i0 = (mt * 4 + nt) * 4 + half * 2;
                    float a0 = ex[w4 * 2048 + i0 * 32 + lane];
                    float a1 = ex[w4 * 2048 + (i0 + 1) * 32 + lane];
                    float g0 = 0.5f * a0 * (1.0f + erff(a0 * 0.70710678118654752f));
                    float g1 = 0.5f * a1 * (1.0f + erff(a1 * 0.70710678118654752f));
                    float h0 = g0 * b0, h1 = g1 * b1;
                    __nv_bfloat16 x0 = __float2bfloat16(h0);
                    __nv_bfloat16 x1 = __float2bfloat16(h1);
                    __nv_bfloat16 l0 = __float2bfloat16(h0 - __bfloat162float(x0));
                    __nv_bfloat16 l1 = __float2bfloat16(h1 - __bfloat162float(x1));
                    union { uint32_t u; __nv_bfloat16 h[2]; } uh, ul;
                    uh.h[0] = x0; uh.h[1] = x1;
                    ul.h[0] = l0; ul.h[1] = l1;
                    *(uint32_t*)(outHi + idx) = uh.u;
                    *(uint32_t*)(outLo + idx) = ul.u;
                }
            }
        }
    }
}

// ===========================================================================
// GEMM3: out = (h @ W2) * rw.  CTA 128m x 128n, 8 warps 2m x 4n of 64x32.
// ===========================================================================
__device__ __forceinline__ void g_load_stage(
    uint32_t st,
    const __nv_bfloat16* __restrict__ Ahi, const __nv_bfloat16* __restrict__ Alo,
    const __nv_bfloat16* __restrict__ Bhi, const __nv_bfloat16* __restrict__ Blo,
    long aRow0, long wBase, int n0, int kb, int tid)
{
#pragma unroll
    for (int j = 0; j < 4; j++) {
        int i = tid + j * 256;
        int arr = i >> 9, row = (i >> 2) & 127, c16 = i & 3;
        uint32_t s = st + arr * A_ARR + a_off(row, c16);
        const __nv_bfloat16* g = (arr ? Alo : Ahi) + (aRow0 + row) * (long)F_ + kb + c16 * 8;
        CP_ASYNC16(s, g);
    }
#pragma unroll
    for (int j = 0; j < 4; j++) {
        int i = tid + j * 256;
        int arr = i >> 9, row = (i >> 4) & 31, c16 = i & 15;
        uint32_t s = st + 2 * A_ARR + arr * GB_ARR + gb_off(row, c16);
        const __nv_bfloat16* g = (arr ? Blo : Bhi)
            + wBase + (long)(kb + row) * D_ + n0 + c16 * 8;
        CP_ASYNC16(s, g);
    }
}

__global__ __launch_bounds__(256, 2)
void gemm3_kernel(const __nv_bfloat16* __restrict__ Ahi,
                  const __nv_bfloat16* __restrict__ Alo,
                  const __nv_bfloat16* __restrict__ Bhi,
                  const __nv_bfloat16* __restrict__ Blo,
                  const int* __restrict__ langs,
                  float* __restrict__ outF)
{
    extern __shared__ char smem[];
    const uint32_t sbase = smem_to_u32(smem);

    const int tid = threadIdx.x;
    const int wid = tid >> 5;
    const int lane = tid & 31;
    const int wm = wid >> 2;
    const int wn = wid & 3;

    const int bz = blockIdx.z;
    const int m0 = blockIdx.y * 128;
    const int n0 = blockIdx.x * 128;

    const int lang = langs[bz];
    int e = lang - 4; if (e < 0) e = 0; if (e > 7) e = 7;
    const int cnt = (lang > 3) ? 1 : 0;
    const float rw = (cnt == 0) ? 1.0f : (1.0f / (float)cnt);

    const long aRow0 = (long)bz * S_ + m0;
    const long wBase = (long)e * F_ * D_;
    const int NC = F_ / BK;    // 128

    float acc[4][4][4];
#pragma unroll
    for (int i = 0; i < 4; i++)
#pragma unroll
        for (int j = 0; j < 4; j++)
#pragma unroll
            for (int q = 0; q < 4; q++) acc[i][j][q] = 0.0f;

    g_load_stage(sbase, Ahi, Alo, Bhi, Blo, aRow0, wBase, n0, 0, tid);
    CP_COMMIT();
    g_load_stage(sbase + G_STAGE, Ahi, Alo, Bhi, Blo, aRow0, wBase, n0, BK, tid);
    CP_COMMIT();

    int sIdx = 0, sNext = 2;

    for (int c = 0; c < NC; ++c) {
        CP_WAIT1();
        __syncthreads();
        if (c + 2 < NC)
            g_load_stage(sbase + sNext * G_STAGE, Ahi, Alo, Bhi, Blo,
                         aRow0, wBase, n0, (c + 2) * BK, tid);
        CP_COMMIT();

        const uint32_t st = sbase + sIdx * G_STAGE;
        const uint32_t stB = st + 2 * A_ARR;
#pragma unroll
        for (int ks = 0; ks < 2; ks++) {
            uint32_t bhi[4][2], blo[4][2];
#pragma unroll
            for (int half = 0; half < 2; half++) {
                int brow = ks * 16 + (lane & 15);
                int bc = wn * 4 + half * 2 + (lane >> 4);
                uint32_t addr = stB + gb_off(brow, bc);
                uint32_t r0, r1, r2, r3;
                ldsm_x4_t(r0, r1, r2, r3, addr);
                bhi[half * 2][0] = r0; bhi[half * 2][1] = r1;
                bhi[half * 2 + 1][0] = r2; bhi[half * 2 + 1][1] = r3;
                ldsm_x4_t(r0, r1, r2, r3, addr + GB_ARR);
                blo[half * 2][0] = r0; blo[half * 2][1] = r1;
                blo[half * 2 + 1][0] = r2; blo[half * 2 + 1][1] = r3;
            }
#pragma unroll
            for (int mt = 0; mt < 4; mt++) {
                int row = wm * 64 + mt * 16 + (lane & 15);
                uint32_t off = a_off(row, ks * 2 + (lane >> 4));
                uint32_t ah[4], al[4];
                ldsm_x4(ah[0], ah[1], ah[2], ah[3], st + off);
                ldsm_x4(al[0], al[1], al[2], al[3], st + A_ARR + off);
#pragma unroll
                for (int nt = 0; nt < 4; nt++) {
                    mma_16816(acc[mt][nt], ah, bhi[nt]);
                    mma_16816(acc[mt][nt], ah, blo[nt]);
                    mma_16816(acc[mt][nt], al, bhi[nt]);
                }
            }
        }
        sIdx = (sIdx == 2) ? 0 : sIdx + 1;
        sNext = (sNext == 2) ? 0 : sNext + 1;
    }

    const int qr = lane >> 2;
    const int qc = (lane & 3) * 2;
#pragma unroll
    for (int mt = 0; mt < 4; mt++) {
#pragma unroll
        for (int half = 0; half < 2; half++) {
            const int gm = m0 + wm * 64 + mt * 16 + qr + half * 8;
            const long rowBase = ((long)bz * S_ + gm) * (long)D_;
#pragma unroll
            for (int nt = 0; nt < 4; nt++) {
                const int gn = n0 + wn * 32 + nt * 8 + qc;
                *(float2*)(outF + rowBase + gn) =
                    make_float2(acc[mt][nt][half * 2] * rw, acc[mt][nt][half * 2 + 1] * rw);
            }
        }
    }
}

// ---------------------------------------------------------------------------
// Launch
// ---------------------------------------------------------------------------
extern "C" void kernel_launch(void* const* d_in, const int* in_sizes, int n_in,
                              void* d_out, int out_size)
{
    const float* x     = (const float*)d_in[0];
    const float* w1    = (const float*)d_in[1];
    const float* w2    = (const float*)d_in[2];
    const float* w3    = (const float*)d_in[3];
    const int*   langs = (const int*)  d_in[4];
    float* out = (float*)d_out;

    __nv_bfloat16 *xhi, *xlo, *w1hi, *w1lo, *w3hi, *w3lo, *w2hi, *w2lo, *hhi, *hlo;
    cudaGetSymbolAddress((void**)&xhi,  g_xhi);
    cudaGetSymbolAddress((void**)&xlo,  g_xlo);
    cudaGetSymbolAddress((void**)&w1hi, g_w1hi);
    cudaGetSymbolAddress((void**)&w1lo, g_w1lo);
    cudaGetSymbolAddress((void**)&w3hi, g_w3hi);
    cudaGetSymbolAddress((void**)&w3lo, g_w3lo);
    cudaGetSymbolAddress((void**)&w2hi, g_w2hi);
    cudaGetSymbolAddress((void**)&w2lo, g_w2lo);
    cudaGetSymbolAddress((void**)&hhi,  g_hhi);
    cudaGetSymbolAddress((void**)&hlo,  g_hlo);

    cudaFuncSetAttribute(fused_gemm12_kernel,
                         cudaFuncAttributeMaxDynamicSharedMemorySize, F_SMEM);
    cudaFuncSetAttribute(gemm3_kernel,
                         cudaFuncAttributeMaxDynamicSharedMemorySize, G_SMEM);

    // 0) expert usage mask
    mask_kernel<<<1, 32>>>(langs);

    // 1) splits
    {
        long nx = (long)B_ * S_ * D_ / 4;
        split_kernel<<<(unsigned)(nx / 256), 256>>>(x, xhi, xlo, nx);
        unsigned wb = (unsigned)(((long)D_ * F_ / 4) / 256);   // 4096 blocks/expert
        dim3 gw(wb, 1, E_);
        split_w_kernel<<<gw, 256>>>(w1, w1hi, w1lo);
        split_w_kernel<<<gw, 256>>>(w3, w3hi, w3lo);
        split_w_kernel<<<gw, 256>>>(w2, w2hi, w2lo);
    }
    // 2) fused GEMM1+GEMM2 + GLU
    {
        dim3 grid(F_ / 64, S_ / 128, B_);
        fused_gemm12_kernel<<<grid, 256, F_SMEM>>>(
            xhi, xlo, w1hi, w1lo, w3hi, w3lo, langs, hhi, hlo);
    }
    // 3) GEMM3
    {
        dim3 grid(D_ / 128, S_ / 128, B_);
        gemm3_kernel<<<grid, 256, G_SMEM>>>(
            hhi, hlo, w2hi, w2lo, langs, out);
    }
}

// round 7
// speedup vs baseline: 4.3893x; 1.3615x over previous
#include <cuda_runtime.h>
#include <cuda_fp16.h>
#include <math.h>
#include <stdint.h>

// ---------------------------------------------------------------------------
#define B_ 8
#define S_ 2048
#define D_ 1024
#define F_ 4096
#define E_ 8

// ---------------------------------------------------------------------------
// Scratch (__device__ globals). Weights single fp16, K-major.
// ---------------------------------------------------------------------------
__device__ __half g_xhi[(size_t)B_ * S_ * D_];
__device__ __half g_xlo[(size_t)B_ * S_ * D_];
__device__ __half g_w1f[(size_t)E_ * D_ * F_];
__device__ __half g_w3f[(size_t)E_ * D_ * F_];
__device__ __half g_w2f[(size_t)E_ * F_ * D_];
__device__ __half g_hhi[(size_t)B_ * S_ * F_];
__device__ __half g_hlo[(size_t)B_ * S_ * F_];
__device__ float  g_p0[(size_t)B_ * S_ * D_];
__device__ float  g_p1[(size_t)B_ * S_ * D_];

// ---------------------------------------------------------------------------
// PTX helpers (base-target-safe)
// ---------------------------------------------------------------------------
__device__ __forceinline__ uint32_t smem_to_u32(const void* p) {
    uint32_t a;
    asm("{ .reg .u64 t; cvta.to.shared.u64 t, %1; cvt.u32.u64 %0, t; }" : "=r"(a) : "l"(p));
    return a;
}
#define CP_ASYNC16(saddr, gptr) \
    asm volatile("cp.async.cg.shared.global [%0], [%1], 16;" :: "r"(saddr), "l"(gptr))
#define CP_COMMIT()  asm volatile("cp.async.commit_group;" ::: "memory")
#define CP_WAIT1()   asm volatile("cp.async.wait_group 1;" ::: "memory")

__device__ __forceinline__ void ldsm_x4(uint32_t& r0, uint32_t& r1, uint32_t& r2,
                                        uint32_t& r3, uint32_t addr) {
    asm volatile("ldmatrix.sync.aligned.m8n8.x4.shared.b16 {%0,%1,%2,%3}, [%4];"
                 : "=r"(r0), "=r"(r1), "=r"(r2), "=r"(r3) : "r"(addr));
}
__device__ __forceinline__ void ldsm_x4_t(uint32_t& r0, uint32_t& r1, uint32_t& r2,
                                          uint32_t& r3, uint32_t addr) {
    asm volatile("ldmatrix.sync.aligned.m8n8.x4.trans.shared.b16 {%0,%1,%2,%3}, [%4];"
                 : "=r"(r0), "=r"(r1), "=r"(r2), "=r"(r3) : "r"(addr));
}
__device__ __forceinline__ void mma_16816(float* d, const uint32_t* a, const uint32_t* b) {
    asm volatile(
        "mma.sync.aligned.m16n8k16.row.col.f32.f16.f16.f32 "
        "{%0,%1,%2,%3}, {%4,%5,%6,%7}, {%8,%9}, {%0,%1,%2,%3};"
        : "+f"(d[0]), "+f"(d[1]), "+f"(d[2]), "+f"(d[3])
        : "r"(a[0]), "r"(a[1]), "r"(a[2]), "r"(a[3]), "r"(b[0]), "r"(b[1]));
}

// ---------------------------------------------------------------------------
// Prep kernels
// ---------------------------------------------------------------------------
__global__ __launch_bounds__(256)
void split_x_kernel(const float* __restrict__ src,
                    __half* __restrict__ hi,
                    __half* __restrict__ lo, long n4)
{
    long i = (long)blockIdx.x * blockDim.x + threadIdx.x;
    if (i >= n4) return;
    float4 v = ((const float4*)src)[i];
    union { uint2 u; __half h[4]; } ph, pl;
    float vv[4] = {v.x, v.y, v.z, v.w};
#pragma unroll
    for (int j = 0; j < 4; j++) {
        __half h = __float2half_rn(vv[j]);
        ph.h[j] = h;
        pl.h[j] = __float2half_rn(vv[j] - __half2float(h));
    }
    ((uint2*)hi)[i] = ph.u;
    ((uint2*)lo)[i] = pl.u;
}

// single-fp16 weight conversion; converts all 3 weight tensors, expert-gated.
// grid: (blocksPerExpert, 3, E_)   y: 0=w1, 1=w3, 2=w2
__global__ __launch_bounds__(256)
void convert_w_kernel(const float* __restrict__ w1,
                      const float* __restrict__ w3,
                      const float* __restrict__ w2,
                      __half* __restrict__ w1f,
                      __half* __restrict__ w3f,
                      __half* __restrict__ w2f,
                      const int* __restrict__ langs)
{
    const int e = blockIdx.z;
    int used = 0;
#pragma unroll
    for (int b = 0; b < B_; b++)
        if (langs[b] - 4 == e) used = 1;
    if (!used) return;
    const long per = (long)D_ * F_ / 4;
    long i = e * per + (long)blockIdx.x * blockDim.x + threadIdx.x;
    const float* src = (blockIdx.y == 0) ? w1 : (blockIdx.y == 1) ? w3 : w2;
    __half* dst = (blockIdx.y == 0) ? w1f : (blockIdx.y == 1) ? w3f : w2f;
    float4 v = ((const float4*)src)[i];
    union { uint2 u; __half h[4]; } p;
    p.h[0] = __float2half_rn(v.x);
    p.h[1] = __float2half_rn(v.y);
    p.h[2] = __float2half_rn(v.z);
    p.h[3] = __float2half_rn(v.w);
    ((uint2*)dst)[i] = p.u;
}

// ---------------------------------------------------------------------------
// Layout constants (swizzled, no padding)
// ---------------------------------------------------------------------------
#define BK 32
#define A_ARR 8192                     // 128 rows x 64B
#define FB_ARR 4096                    // 32 rows x 128B
#define F_STAGE (2*A_ARR + 2*FB_ARR)   // 24576
#define F_SMEM  (3 * F_STAGE)          // 73728
#define GB_ARR 8192                    // 32 rows x 256B
#define G_STAGE (2*A_ARR + GB_ARR)     // 24576
#define G_SMEM  (3 * G_STAGE)          // 73728

__device__ __forceinline__ uint32_t a_off(int row, int q) {
    return (uint32_t)(row * 64 + ((q ^ ((row >> 1) & 3)) << 4));
}
__device__ __forceinline__ uint32_t fb_off(int row, int c) {
    return (uint32_t)(row * 128 + ((c ^ (row & 7)) << 4));
}
__device__ __forceinline__ uint32_t gb_off(int row, int c) {
    return (uint32_t)(row * 256 + ((c ^ (row & 7)) << 4));
}

// ===========================================================================
// FUSED: a = x@W1, b = x@W3; h = gelu(a)*b -> fp16 hi/lo
// CTA 128m x 64n x 2 outputs, 8 warps: out_sel=wid>>2; wm=(wid&3)>>1, wn=wid&1.
// A = x in 2 fp16 terms; B = single fp16 weight. 2 MMA passes.
// ===========================================================================
__device__ __forceinline__ void f_load_stage(
    uint32_t st,
    const __half* __restrict__ Ahi, const __half* __restrict__ Alo,
    const __half* __restrict__ B1, const __half* __restrict__ B3,
    long aRow0, long wBase, int n0, int kb, int tid)
{
#pragma unroll
    for (int j = 0; j < 4; j++) {        // A: 2 arrays x 128 rows x 4 chunks
        int i = tid + j * 256;
        int arr = i >> 9, row = (i >> 2) & 127, c16 = i & 3;
        uint32_t s = st + arr * A_ARR + a_off(row, c16);
        const __half* g = (arr ? Alo : Ahi) + (aRow0 + row) * (long)D_ + kb + c16 * 8;
        CP_ASYNC16(s, g);
    }
#pragma unroll
    for (int j = 0; j < 2; j++) {        // B: 2 arrays x 32 rows x 8 chunks
        int i = tid + j * 256;
        int arr = i >> 8, row = (i >> 3) & 31, c16 = i & 7;
        uint32_t s = st + 2 * A_ARR + arr * FB_ARR + fb_off(row, c16);
        const __half* g = (arr ? B3 : B1)
            + wBase + (long)(kb + row) * F_ + n0 + c16 * 8;
        CP_ASYNC16(s, g);
    }
}

__global__ __launch_bounds__(256, 2)
void fused_gemm12_kernel(const __half* __restrict__ Ahi,
                         const __half* __restrict__ Alo,
                         const __half* __restrict__ B1,
                         const __half* __restrict__ B3,
                         const int* __restrict__ langs,
                         __half* __restrict__ outHi,
                         __half* __restrict__ outLo)
{
    extern __shared__ char smem[];
    const uint32_t sbase = smem_to_u32(smem);

    const int tid = threadIdx.x;
    const int wid = tid >> 5;
    const int lane = tid & 31;
    const int out_sel = wid >> 2;          // 0: W1(a), 1: W3(b)
    const int w4 = wid & 3;
    const int wm = w4 >> 1;
    const int wn = w4 & 1;

    const int bz = blockIdx.z;
    const int m0 = blockIdx.y * 128;
    const int n0 = blockIdx.x * 64;

    const int lang = langs[bz];
    int e = lang - 4; if (e < 0) e = 0; if (e > 7) e = 7;

    const long aRow0 = (long)bz * S_ + m0;
    const long wBase = (long)e * D_ * F_;
    const int NC = D_ / BK;    // 32

    float acc[4][4][4];
#pragma unroll
    for (int i = 0; i < 4; i++)
#pragma unroll
        for (int j = 0; j < 4; j++)
#pragma unroll
            for (int q = 0; q < 4; q++) acc[i][j][q] = 0.0f;

    f_load_stage(sbase, Ahi, Alo, B1, B3, aRow0, wBase, n0, 0, tid);
    CP_COMMIT();
    f_load_stage(sbase + F_STAGE, Ahi, Alo, B1, B3, aRow0, wBase, n0, BK, tid);
    CP_COMMIT();

    const uint32_t stBoff = 2 * A_ARR + out_sel * FB_ARR;
    int sIdx = 0, sNext = 2;

    for (int c = 0; c < NC; ++c) {
        CP_WAIT1();
        __syncthreads();
        if (c + 2 < NC)
            f_load_stage(sbase + sNext * F_STAGE, Ahi, Alo, B1, B3,
                         aRow0, wBase, n0, (c + 2) * BK, tid);
        CP_COMMIT();

        const uint32_t st = sbase + sIdx * F_STAGE;
        const uint32_t stB = st + stBoff;
#pragma unroll
        for (int ks = 0; ks < 2; ks++) {
            uint32_t bf[4][2];
#pragma unroll
            for (int half = 0; half < 2; half++) {
                int brow = ks * 16 + (lane & 15);
                int bc = wn * 4 + half * 2 + (lane >> 4);
                uint32_t r0, r1, r2, r3;
                ldsm_x4_t(r0, r1, r2, r3, stB + fb_off(brow, bc));
                bf[half * 2][0] = r0; bf[half * 2][1] = r1;
                bf[half * 2 + 1][0] = r2; bf[half * 2 + 1][1] = r3;
            }
#pragma unroll
            for (int mt = 0; mt < 4; mt++) {
                int row = wm * 64 + mt * 16 + (lane & 15);
                uint32_t off = a_off(row, ks * 2 + (lane >> 4));
                uint32_t ah[4], al[4];
                ldsm_x4(ah[0], ah[1], ah[2], ah[3], st + off);
                ldsm_x4(al[0], al[1], al[2], al[3], st + A_ARR + off);
#pragma unroll
                for (int nt = 0; nt < 4; nt++) {
                    mma_16816(acc[mt][nt], ah, bf[nt]);
                    mma_16816(acc[mt][nt], al, bf[nt]);
                }
            }
        }
        sIdx = (sIdx == 2) ? 0 : sIdx + 1;
        sNext = (sNext == 2) ? 0 : sNext + 1;
    }

    // --- epilogue: a-warps dump acc to smem; b-warps apply gelu(a)*b ---
    __syncthreads();
    float* ex = (float*)smem;              // 32 KB needed; 72 KB available
    if (out_sel == 0) {
#pragma unroll
        for (int mt = 0; mt < 4; mt++)
#pragma unroll
            for (int nt = 0; nt < 4; nt++)
#pragma unroll
                for (int q = 0; q < 4; q++) {
                    int i = (mt * 4 + nt) * 4 + q;
                    ex[w4 * 2048 + i * 32 + lane] = acc[mt][nt][q];
                }
    }
    __syncthreads();
    if (out_sel == 1) {
        const int qr = lane >> 2;
        const int qc = (lane & 3) * 2;
#pragma unroll
        for (int mt = 0; mt < 4; mt++) {
#pragma unroll
            for (int half = 0; half < 2; half++) {
                const int gm = m0 + wm * 64 + mt * 16 + qr + half * 8;
                const long rowBase = ((long)bz * S_ + gm) * (long)F_;
#pragma unroll
                for (int nt = 0; nt < 4; nt++) {
                    const int gn = n0 + wn * 32 + nt * 8 + qc;
                    const long idx = rowBase + gn;
                    float b0 = acc[mt][nt][half * 2 + 0];
                    float b1 = acc[mt][nt][half * 2 + 1];
                    int i0 = (mt * 4 + nt) * 4 + half * 2;
                    float a0 = ex[w4 * 2048 + i0 * 32 + lane];
                    float a1 = ex[w4 * 2048 + (i0 + 1) * 32 + lane];
                    float g0 = 0.5f * a0 * (1.0f + erff(a0 * 0.70710678118654752f));
                    float g1 = 0.5f * a1 * (1.0f + erff(a1 * 0.70710678118654752f));
                    float h0 = g0 * b0, h1 = g1 * b1;
                    __half x0 = __float2half_rn(h0);
                    __half x1 = __float2half_rn(h1);
                    __half l0 = __float2half_rn(h0 - __half2float(x0));
                    __half l1 = __float2half_rn(h1 - __half2float(x1));
                    union { uint32_t u; __half h[2]; } uh, ul;
                    uh.h[0] = x0; uh.h[1] = x1;
                    ul.h[0] = l0; ul.h[1] = l1;
                    *(uint32_t*)(outHi + idx) = uh.u;
                    *(uint32_t*)(outLo + idx) = ul.u;
                }
            }
        }
    }
}

// ===========================================================================
// GEMM3 (split-K=2): p[half] = h[.., Khalf] @ W2[Khalf, ..]
// CTA 128m x 128n, 8 warps 2m x 4n of 64x32. A = h hi/lo fp16, B single fp16.
// ===========================================================================
__device__ __forceinline__ void g_load_stage(
    uint32_t st,
    const __half* __restrict__ Ahi, const __half* __restrict__ Alo,
    const __half* __restrict__ Bf,
    long aRow0, long wBase, int n0, int kb, int tid)
{
#pragma unroll
    for (int j = 0; j < 4; j++) {
        int i = tid + j * 256;
        int arr = i >> 9, row = (i >> 2) & 127, c16 = i & 3;
        uint32_t s = st + arr * A_ARR + a_off(row, c16);
        const __half* g = (arr ? Alo : Ahi) + (aRow0 + row) * (long)F_ + kb + c16 * 8;
        CP_ASYNC16(s, g);
    }
#pragma unroll
    for (int j = 0; j < 2; j++) {
        int i = tid + j * 256;
        int row = (i >> 4) & 31, c16 = i & 15;
        uint32_t s = st + 2 * A_ARR + gb_off(row, c16);
        const __half* g = Bf + wBase + (long)(kb + row) * D_ + n0 + c16 * 8;
        CP_ASYNC16(s, g);
    }
}

__global__ __launch_bounds__(256, 2)
void gemm3_kernel(const __half* __restrict__ Ahi,
                  const __half* __restrict__ Alo,
                  const __half* __restrict__ Bf,
                  const int* __restrict__ langs,
                  float* __restrict__ p0,
                  float* __restrict__ p1)
{
    extern __shared__ char smem[];
    const uint32_t sbase = smem_to_u32(smem);

    const int tid = threadIdx.x;
    const int wid = tid >> 5;
    const int lane = tid & 31;
    const int wm = wid >> 2;
    const int wn = wid & 3;

    const int z = blockIdx.z;
    const int bz = z >> 1;
    const int kh = z & 1;                 // K half
    const int m0 = blockIdx.y * 128;
    const int n0 = blockIdx.x * 128;
    float* __restrict__ outP = kh ? p1 : p0;

    const int lang = langs[bz];
    int e = lang - 4; if (e < 0) e = 0; if (e > 7) e = 7;

    const long aRow0 = (long)bz * S_ + m0;
    const long wBase = (long)e * F_ * D_;
    const int kBase = kh * (F_ / 2);
    const int NC = (F_ / 2) / BK;         // 64

    float acc[4][4][4];
#pragma unroll
    for (int i = 0; i < 4; i++)
#pragma unroll
        for (int j = 0; j < 4; j++)
#pragma unroll
            for (int q = 0; q < 4; q++) acc[i][j][q] = 0.0f;

    g_load_stage(sbase, Ahi, Alo, Bf, aRow0, wBase, n0, kBase, tid);
    CP_COMMIT();
    g_load_stage(sbase + G_STAGE, Ahi, Alo, Bf, aRow0, wBase, n0, kBase + BK, tid);
    CP_COMMIT();

    int sIdx = 0, sNext = 2;

    for (int c = 0; c < NC; ++c) {
        CP_WAIT1();
        __syncthreads();
        if (c + 2 < NC)
            g_load_stage(sbase + sNext * G_STAGE, Ahi, Alo, Bf,
                         aRow0, wBase, n0, kBase + (c + 2) * BK, tid);
        CP_COMMIT();

        const uint32_t st = sbase + sIdx * G_STAGE;
        const uint32_t stB = st + 2 * A_ARR;
#pragma unroll
        for (int ks = 0; ks < 2; ks++) {
            uint32_t bf[4][2];
#pragma unroll
            for (int half = 0; half < 2; half++) {
                int brow = ks * 16 + (lane & 15);
                int bc = wn * 4 + half * 2 + (lane >> 4);
                uint32_t r0, r1, r2, r3;
                ldsm_x4_t(r0, r1, r2, r3, stB + gb_off(brow, bc));
                bf[half * 2][0] = r0; bf[half * 2][1] = r1;
                bf[half * 2 + 1][0] = r2; bf[half * 2 + 1][1] = r3;
            }
#pragma unroll
            for (int mt = 0; mt < 4; mt++) {
                int row = wm * 64 + mt * 16 + (lane & 15);
                uint32_t off = a_off(row, ks * 2 + (lane >> 4));
                uint32_t ah[4], al[4];
                ldsm_x4(ah[0], ah[1], ah[2], ah[3], st + off);
                ldsm_x4(al[0], al[1], al[2], al[3], st + A_ARR + off);
#pragma unroll
                for (int nt = 0; nt < 4; nt++) {
                    mma_16816(acc[mt][nt], ah, bf[nt]);
                    mma_16816(acc[mt][nt], al, bf[nt]);
                }
            }
        }
        sIdx = (sIdx == 2) ? 0 : sIdx + 1;
        sNext = (sNext == 2) ? 0 : sNext + 1;
    }

    const int qr = lane >> 2;
    const int qc = (lane & 3) * 2;
#pragma unroll
    for (int mt = 0; mt < 4; mt++) {
#pragma unroll
        for (int half = 0; half < 2; half++) {
            const int gm = m0 + wm * 64 + mt * 16 + qr + half * 8;
            const long rowBase = ((long)bz * S_ + gm) * (long)D_;
#pragma unroll
            for (int nt = 0; nt < 4; nt++) {
                const int gn = n0 + wn * 32 + nt * 8 + qc;
                *(float2*)(outP + rowBase + gn) =
                    make_float2(acc[mt][nt][half * 2], acc[mt][nt][half * 2 + 1]);
            }
        }
    }
}

// ---------------------------------------------------------------------------
// Reduce: out = (p0 + p1) * rw
// ---------------------------------------------------------------------------
__global__ __launch_bounds__(256)
void reduce_kernel(const float* __restrict__ p0, const float* __restrict__ p1,
                   const int* __restrict__ langs, float* __restrict__ out, long n4)
{
    long i = (long)blockIdx.x * blockDim.x + threadIdx.x;
    if (i >= n4) return;
    const long perB4 = (long)S_ * D_ / 4;
    int bz = (int)(i / perB4);
    const int lang = langs[bz];
    const int cnt = (lang > 3) ? 1 : 0;
    const float rw = (cnt == 0) ? 1.0f : (1.0f / (float)cnt);
    float4 a = ((const float4*)p0)[i];
    float4 b = ((const float4*)p1)[i];
    ((float4*)out)[i] = make_float4((a.x + b.x) * rw, (a.y + b.y) * rw,
                                    (a.z + b.z) * rw, (a.w + b.w) * rw);
}

// ---------------------------------------------------------------------------
// Launch
// ---------------------------------------------------------------------------
extern "C" void kernel_launch(void* const* d_in, const int* in_sizes, int n_in,
                              void* d_out, int out_size)
{
    const float* x     = (const float*)d_in[0];
    const float* w1    = (const float*)d_in[1];
    const float* w2    = (const float*)d_in[2];
    const float* w3    = (const float*)d_in[3];
    const int*   langs = (const int*)  d_in[4];
    float* out = (float*)d_out;

    __half *xhi, *xlo, *w1f, *w3f, *w2f, *hhi, *hlo;
    float *p0, *p1;
    cudaGetSymbolAddress((void**)&xhi, g_xhi);
    cudaGetSymbolAddress((void**)&xlo, g_xlo);
    cudaGetSymbolAddress((void**)&w1f, g_w1f);
    cudaGetSymbolAddress((void**)&w3f, g_w3f);
    cudaGetSymbolAddress((void**)&w2f, g_w2f);
    cudaGetSymbolAddress((void**)&hhi, g_hhi);
    cudaGetSymbolAddress((void**)&hlo, g_hlo);
    cudaGetSymbolAddress((void**)&p0,  g_p0);
    cudaGetSymbolAddress((void**)&p1,  g_p1);

    cudaFuncSetAttribute(fused_gemm12_kernel,
                         cudaFuncAttributeMaxDynamicSharedMemorySize, F_SMEM);
    cudaFuncSetAttribute(gemm3_kernel,
                         cudaFuncAttributeMaxDynamicSharedMemorySize, G_SMEM);

    // 1) prep: x split (2-term fp16) + weight conversion (1-term fp16, gated)
    {
        long nx = (long)B_ * S_ * D_ / 4;
        split_x_kernel<<<(unsigned)(nx / 256), 256>>>(x, xhi, xlo, nx);
        unsigned wb = (unsigned)(((long)D_ * F_ / 4) / 256);
        dim3 gw(wb, 3, E_);
        convert_w_kernel<<<gw, 256>>>(w1, w3, w2, w1f, w3f, w2f, langs);
    }
    // 2) fused GEMM1+GEMM2 + GLU -> h (fp16 hi/lo)
    {
        dim3 grid(F_ / 64, S_ / 128, B_);
        fused_gemm12_kernel<<<grid, 256, F_SMEM>>>(
            xhi, xlo, w1f, w3f, langs, hhi, hlo);
    }
    // 3) GEMM3 split-K=2 -> partials
    {
        dim3 grid(D_ / 128, S_ / 128, B_ * 2);
        gemm3_kernel<<<grid, 256, G_SMEM>>>(hhi, hlo, w2f, langs, p0, p1);
    }
    // 4) reduce + routing weight
    {
        long n4 = (long)B_ * S_ * D_ / 4;
        reduce_kernel<<<(unsigned)(n4 / 256), 256>>>(p0, p1, langs, out, n4);
    }
}

// round 8
// speedup vs baseline: 7.6587x; 1.7449x over previous
#include <cuda_runtime.h>
#include <cuda_fp16.h>
#include <math.h>
#include <stdint.h>

// ---------------------------------------------------------------------------
#define B_ 8
#define S_ 2048
#define D_ 1024
#define F_ 4096
#define E_ 8

// ---------------------------------------------------------------------------
// Scratch (__device__ globals). Everything single fp16, K-major.
// ---------------------------------------------------------------------------
__device__ __half g_xf[(size_t)B_ * S_ * D_];
__device__ __half g_w1f[(size_t)E_ * D_ * F_];
__device__ __half g_w3f[(size_t)E_ * D_ * F_];
__device__ __half g_w2f[(size_t)E_ * F_ * D_];
__device__ __half g_hf[(size_t)B_ * S_ * F_];
__device__ float  g_p0[(size_t)B_ * S_ * D_];
__device__ float  g_p1[(size_t)B_ * S_ * D_];

// ---------------------------------------------------------------------------
// PTX helpers (base-target-safe)
// ---------------------------------------------------------------------------
__device__ __forceinline__ uint32_t smem_to_u32(const void* p) {
    uint32_t a;
    asm("{ .reg .u64 t; cvta.to.shared.u64 t, %1; cvt.u32.u64 %0, t; }" : "=r"(a) : "l"(p));
    return a;
}
#define CP_ASYNC16(saddr, gptr) \
    asm volatile("cp.async.cg.shared.global [%0], [%1], 16;" :: "r"(saddr), "l"(gptr))
#define CP_COMMIT()  asm volatile("cp.async.commit_group;" ::: "memory")
#define CP_WAIT1()   asm volatile("cp.async.wait_group 1;" ::: "memory")

__device__ __forceinline__ void ldsm_x4(uint32_t& r0, uint32_t& r1, uint32_t& r2,
                                        uint32_t& r3, uint32_t addr) {
    asm volatile("ldmatrix.sync.aligned.m8n8.x4.shared.b16 {%0,%1,%2,%3}, [%4];"
                 : "=r"(r0), "=r"(r1), "=r"(r2), "=r"(r3) : "r"(addr));
}
__device__ __forceinline__ void ldsm_x4_t(uint32_t& r0, uint32_t& r1, uint32_t& r2,
                                          uint32_t& r3, uint32_t addr) {
    asm volatile("ldmatrix.sync.aligned.m8n8.x4.trans.shared.b16 {%0,%1,%2,%3}, [%4];"
                 : "=r"(r0), "=r"(r1), "=r"(r2), "=r"(r3) : "r"(addr));
}
__device__ __forceinline__ void mma_16816(float* d, const uint32_t* a, const uint32_t* b) {
    asm volatile(
        "mma.sync.aligned.m16n8k16.row.col.f32.f16.f16.f32 "
        "{%0,%1,%2,%3}, {%4,%5,%6,%7}, {%8,%9}, {%0,%1,%2,%3};"
        : "+f"(d[0]), "+f"(d[1]), "+f"(d[2]), "+f"(d[3])
        : "r"(a[0]), "r"(a[1]), "r"(a[2]), "r"(a[3]), "r"(b[0]), "r"(b[1]));
}

// ---------------------------------------------------------------------------
// Prep kernels
// ---------------------------------------------------------------------------
__global__ __launch_bounds__(256)
void convert_x_kernel(const float* __restrict__ src, __half* __restrict__ dst, long n4)
{
    long i = (long)blockIdx.x * blockDim.x + threadIdx.x;
    if (i >= n4) return;
    float4 v = ((const float4*)src)[i];
    union { uint2 u; __half h[4]; } p;
    p.h[0] = __float2half_rn(v.x);
    p.h[1] = __float2half_rn(v.y);
    p.h[2] = __float2half_rn(v.z);
    p.h[3] = __float2half_rn(v.w);
    ((uint2*)dst)[i] = p.u;
}

// weight conversion, expert-gated.  grid: (blocksPerExpert, 3, E_)
__global__ __launch_bounds__(256)
void convert_w_kernel(const float* __restrict__ w1,
                      const float* __restrict__ w3,
                      const float* __restrict__ w2,
                      __half* __restrict__ w1f,
                      __half* __restrict__ w3f,
                      __half* __restrict__ w2f,
                      const int* __restrict__ langs)
{
    const int e = blockIdx.z;
    int used = 0;
#pragma unroll
    for (int b = 0; b < B_; b++)
        if (langs[b] - 4 == e) used = 1;
    if (!used) return;
    const long per = (long)D_ * F_ / 4;
    long i = e * per + (long)blockIdx.x * blockDim.x + threadIdx.x;
    const float* src = (blockIdx.y == 0) ? w1 : (blockIdx.y == 1) ? w3 : w2;
    __half* dst = (blockIdx.y == 0) ? w1f : (blockIdx.y == 1) ? w3f : w2f;
    float4 v = ((const float4*)src)[i];
    union { uint2 u; __half h[4]; } p;
    p.h[0] = __float2half_rn(v.x);
    p.h[1] = __float2half_rn(v.y);
    p.h[2] = __float2half_rn(v.z);
    p.h[3] = __float2half_rn(v.w);
    ((uint2*)dst)[i] = p.u;
}

// ---------------------------------------------------------------------------
// Layout constants (swizzled, no padding)
// ---------------------------------------------------------------------------
#define BK 32
#define A_ARR 8192                     // 128 rows x 64B
#define FB_ARR 4096                    // 32 rows x 128B
#define F_STAGE (A_ARR + 2*FB_ARR)     // 16384
#define F_SMEM  (3 * F_STAGE)          // 49152
#define GB_ARR 8192                    // 32 rows x 256B
#define G_STAGE (A_ARR + GB_ARR)       // 16384
#define G_SMEM  (3 * G_STAGE)          // 49152

__device__ __forceinline__ uint32_t a_off(int row, int q) {
    return (uint32_t)(row * 64 + ((q ^ ((row >> 1) & 3)) << 4));
}
__device__ __forceinline__ uint32_t fb_off(int row, int c) {
    return (uint32_t)(row * 128 + ((c ^ (row & 7)) << 4));
}
__device__ __forceinline__ uint32_t gb_off(int row, int c) {
    return (uint32_t)(row * 256 + ((c ^ (row & 7)) << 4));
}

// ===========================================================================
// FUSED: a = x@W1, b = x@W3; h = gelu(a)*b -> fp16
// CTA 128m x 64n x 2 outputs, 8 warps: out_sel=wid>>2; wm=(wid&3)>>1, wn=wid&1.
// Single fp16 pass.  3-stage, one __syncthreads per chunk, 2 CTAs/SM.
// ===========================================================================
__device__ __forceinline__ void f_load_stage(
    uint32_t st,
    const __half* __restrict__ Af,
    const __half* __restrict__ B1, const __half* __restrict__ B3,
    long aRow0, long wBase, int n0, int kb, int tid)
{
#pragma unroll
    for (int j = 0; j < 2; j++) {        // A: 128 rows x 4 chunks
        int i = tid + j * 256;
        int row = (i >> 2) & 127, c16 = i & 3;
        uint32_t s = st + a_off(row, c16);
        CP_ASYNC16(s, Af + (aRow0 + row) * (long)D_ + kb + c16 * 8);
    }
#pragma unroll
    for (int j = 0; j < 2; j++) {        // B: 2 arrays x 32 rows x 8 chunks
        int i = tid + j * 256;
        int arr = i >> 8, row = (i >> 3) & 31, c16 = i & 7;
        uint32_t s = st + A_ARR + arr * FB_ARR + fb_off(row, c16);
        const __half* g = (arr ? B3 : B1)
            + wBase + (long)(kb + row) * F_ + n0 + c16 * 8;
        CP_ASYNC16(s, g);
    }
}

__global__ __launch_bounds__(256, 2)
void fused_gemm12_kernel(const __half* __restrict__ Af,
                         const __half* __restrict__ B1,
                         const __half* __restrict__ B3,
                         const int* __restrict__ langs,
                         __half* __restrict__ outH)
{
    extern __shared__ char smem[];
    const uint32_t sbase = smem_to_u32(smem);

    const int tid = threadIdx.x;
    const int wid = tid >> 5;
    const int lane = tid & 31;
    const int out_sel = wid >> 2;          // 0: W1(a), 1: W3(b)
    const int w4 = wid & 3;
    const int wm = w4 >> 1;
    const int wn = w4 & 1;

    const int bz = blockIdx.z;
    const int m0 = blockIdx.y * 128;
    const int n0 = blockIdx.x * 64;

    const int lang = langs[bz];
    int e = lang - 4; if (e < 0) e = 0; if (e > 7) e = 7;

    const long aRow0 = (long)bz * S_ + m0;
    const long wBase = (long)e * D_ * F_;
    const int NC = D_ / BK;    // 32

    float acc[4][4][4];
#pragma unroll
    for (int i = 0; i < 4; i++)
#pragma unroll
        for (int j = 0; j < 4; j++)
#pragma unroll
            for (int q = 0; q < 4; q++) acc[i][j][q] = 0.0f;

    f_load_stage(sbase, Af, B1, B3, aRow0, wBase, n0, 0, tid);
    CP_COMMIT();
    f_load_stage(sbase + F_STAGE, Af, B1, B3, aRow0, wBase, n0, BK, tid);
    CP_COMMIT();

    const uint32_t stBoff = A_ARR + out_sel * FB_ARR;
    int sIdx = 0, sNext = 2;

    for (int c = 0; c < NC; ++c) {
        CP_WAIT1();
        __syncthreads();
        if (c + 2 < NC)
            f_load_stage(sbase + sNext * F_STAGE, Af, B1, B3,
                         aRow0, wBase, n0, (c + 2) * BK, tid);
        CP_COMMIT();

        const uint32_t st = sbase + sIdx * F_STAGE;
        const uint32_t stB = st + stBoff;
#pragma unroll
        for (int ks = 0; ks < 2; ks++) {
            uint32_t bf[4][2];
#pragma unroll
            for (int half = 0; half < 2; half++) {
                int brow = ks * 16 + (lane & 15);
                int bc = wn * 4 + half * 2 + (lane >> 4);
                uint32_t r0, r1, r2, r3;
                ldsm_x4_t(r0, r1, r2, r3, stB + fb_off(brow, bc));
                bf[half * 2][0] = r0; bf[half * 2][1] = r1;
                bf[half * 2 + 1][0] = r2; bf[half * 2 + 1][1] = r3;
            }
#pragma unroll
            for (int mt = 0; mt < 4; mt++) {
                int row = wm * 64 + mt * 16 + (lane & 15);
                uint32_t off = a_off(row, ks * 2 + (lane >> 4));
                uint32_t af[4];
                ldsm_x4(af[0], af[1], af[2], af[3], st + off);
#pragma unroll
                for (int nt = 0; nt < 4; nt++)
                    mma_16816(acc[mt][nt], af, bf[nt]);
            }
        }
        sIdx = (sIdx == 2) ? 0 : sIdx + 1;
        sNext = (sNext == 2) ? 0 : sNext + 1;
    }

    // --- epilogue: a-warps dump acc to smem; b-warps apply gelu(a)*b ---
    __syncthreads();
    float* ex = (float*)smem;              // 32 KB needed, 48 KB available
    if (out_sel == 0) {
#pragma unroll
        for (int mt = 0; mt < 4; mt++)
#pragma unroll
            for (int nt = 0; nt < 4; nt++)
#pragma unroll
                for (int q = 0; q < 4; q++) {
                    int i = (mt * 4 + nt) * 4 + q;
                    ex[w4 * 2048 + i * 32 + lane] = acc[mt][nt][q];
                }
    }
    __syncthreads();
    if (out_sel == 1) {
        const int qr = lane >> 2;
        const int qc = (lane & 3) * 2;
#pragma unroll
        for (int mt = 0; mt < 4; mt++) {
#pragma unroll
            for (int half = 0; half < 2; half++) {
                const int gm = m0 + wm * 64 + mt * 16 + qr + half * 8;
                const long rowBase = ((long)bz * S_ + gm) * (long)F_;
#pragma unroll
                for (int nt = 0; nt < 4; nt++) {
                    const int gn = n0 + wn * 32 + nt * 8 + qc;
                    const long idx = rowBase + gn;
                    float b0 = acc[mt][nt][half * 2 + 0];
                    float b1 = acc[mt][nt][half * 2 + 1];
                    int i0 = (mt * 4 + nt) * 4 + half * 2;
                    float a0 = ex[w4 * 2048 + i0 * 32 + lane];
                    float a1 = ex[w4 * 2048 + (i0 + 1) * 32 + lane];
                    float g0 = 0.5f * a0 * (1.0f + erff(a0 * 0.70710678118654752f));
                    float g1 = 0.5f * a1 * (1.0f + erff(a1 * 0.70710678118654752f));
                    union { uint32_t u; __half h[2]; } uh;
                    uh.h[0] = __float2half_rn(g0 * b0);
                    uh.h[1] = __float2half_rn(g1 * b1);
                    *(uint32_t*)(outH + idx) = uh.u;
                }
            }
        }
    }
}

// ===========================================================================
// GEMM3 (split-K=2): p[half] = h[.., Khalf] @ W2[Khalf, ..]
// CTA 128m x 128n, 8 warps 2m x 4n of 64x32.  Single fp16 pass.
// ===========================================================================
__device__ __forceinline__ void g_load_stage(
    uint32_t st,
    const __half* __restrict__ Af, const __half* __restrict__ Bf,
    long aRow0, long wBase, int n0, int kb, int tid)
{
#pragma unroll
    for (int j = 0; j < 2; j++) {
        int i = tid + j * 256;
        int row = (i >> 2) & 127, c16 = i & 3;
        uint32_t s = st + a_off(row, c16);
        CP_ASYNC16(s, Af + (aRow0 + row) * (long)F_ + kb + c16 * 8);
    }
#pragma unroll
    for (int j = 0; j < 2; j++) {
        int i = tid + j * 256;
        int row = (i >> 4) & 31, c16 = i & 15;
        uint32_t s = st + A_ARR + gb_off(row, c16);
        CP_ASYNC16(s, Bf + wBase + (long)(kb + row) * D_ + n0 + c16 * 8);
    }
}

__global__ __launch_bounds__(256, 2)
void gemm3_kernel(const __half* __restrict__ Af,
                  const __half* __restrict__ Bf,
                  const int* __restrict__ langs,
                  float* __restrict__ p0,
                  float* __restrict__ p1)
{
    extern __shared__ char smem[];
    const uint32_t sbase = smem_to_u32(smem);

    const int tid = threadIdx.x;
    const int wid = tid >> 5;
    const int lane = tid & 31;
    const int wm = wid >> 2;
    const int wn = wid & 3;

    const int z = blockIdx.z;
    const int bz = z >> 1;
    const int kh = z & 1;
    const int m0 = blockIdx.y * 128;
    const int n0 = blockIdx.x * 128;
    float* __restrict__ outP = kh ? p1 : p0;

    const int lang = langs[bz];
    int e = lang - 4; if (e < 0) e = 0; if (e > 7) e = 7;

    const long aRow0 = (long)bz * S_ + m0;
    const long wBase = (long)e * F_ * D_;
    const int kBase = kh * (F_ / 2);
    const int NC = (F_ / 2) / BK;         // 64

    float acc[4][4][4];
#pragma unroll
    for (int i = 0; i < 4; i++)
#pragma unroll
        for (int j = 0; j < 4; j++)
#pragma unroll
            for (int q = 0; q < 4; q++) acc[i][j][q] = 0.0f;

    g_load_stage(sbase, Af, Bf, aRow0, wBase, n0, kBase, tid);
    CP_COMMIT();
    g_load_stage(sbase + G_STAGE, Af, Bf, aRow0, wBase, n0, kBase + BK, tid);
    CP_COMMIT();

    int sIdx = 0, sNext = 2;

    for (int c = 0; c < NC; ++c) {
        CP_WAIT1();
        __syncthreads();
        if (c + 2 < NC)
            g_load_stage(sbase + sNext * G_STAGE, Af, Bf,
                         aRow0, wBase, n0, kBase + (c + 2) * BK, tid);
        CP_COMMIT();

        const uint32_t st = sbase + sIdx * G_STAGE;
        const uint32_t stB = st + A_ARR;
#pragma unroll
        for (int ks = 0; ks < 2; ks++) {
            uint32_t bf[4][2];
#pragma unroll
            for (int half = 0; half < 2; half++) {
                int brow = ks * 16 + (lane & 15);
                int bc = wn * 4 + half * 2 + (lane >> 4);
                uint32_t r0, r1, r2, r3;
                ldsm_x4_t(r0, r1, r2, r3, stB + gb_off(brow, bc));
                bf[half * 2][0] = r0; bf[half * 2][1] = r1;
                bf[half * 2 + 1][0] = r2; bf[half * 2 + 1][1] = r3;
            }
#pragma unroll
            for (int mt = 0; mt < 4; mt++) {
                int row = wm * 64 + mt * 16 + (lane & 15);
                uint32_t off = a_off(row, ks * 2 + (lane >> 4));
                uint32_t af[4];
                ldsm_x4(af[0], af[1], af[2], af[3], st + off);
#pragma unroll
                for (int nt = 0; nt < 4; nt++)
                    mma_16816(acc[mt][nt], af, bf[nt]);
            }
        }
        sIdx = (sIdx == 2) ? 0 : sIdx + 1;
        sNext = (sNext == 2) ? 0 : sNext + 1;
    }

    const int qr = lane >> 2;
    const int qc = (lane & 3) * 2;
#pragma unroll
    for (int mt = 0; mt < 4; mt++) {
#pragma unroll
        for (int half = 0; half < 2; half++) {
            const int gm = m0 + wm * 64 + mt * 16 + qr + half * 8;
            const long rowBase = ((long)bz * S_ + gm) * (long)D_;
#pragma unroll
            for (int nt = 0; nt < 4; nt++) {
                const int gn = n0 + wn * 32 + nt * 8 + qc;
                *(float2*)(outP + rowBase + gn) =
                    make_float2(acc[mt][nt][half * 2], acc[mt][nt][half * 2 + 1]);
            }
        }
    }
}

// ---------------------------------------------------------------------------
// Reduce: out = (p0 + p1) * rw
// ---------------------------------------------------------------------------
__global__ __launch_bounds__(256)
void reduce_kernel(const float* __restrict__ p0, const float* __restrict__ p1,
                   const int* __restrict__ langs, float* __restrict__ out, long n4)
{
    long i = (long)blockIdx.x * blockDim.x + threadIdx.x;
    if (i >= n4) return;
    const long perB4 = (long)S_ * D_ / 4;
    int bz = (int)(i / perB4);
    const int lang = langs[bz];
    const int cnt = (lang > 3) ? 1 : 0;
    const float rw = (cnt == 0) ? 1.0f : (1.0f / (float)cnt);
    float4 a = ((const float4*)p0)[i];
    float4 b = ((const float4*)p1)[i];
    ((float4*)out)[i] = make_float4((a.x + b.x) * rw, (a.y + b.y) * rw,
                                    (a.z + b.z) * rw, (a.w + b.w) * rw);
}

// ---------------------------------------------------------------------------
// Launch
// ---------------------------------------------------------------------------
extern "C" void kernel_launch(void* const* d_in, const int* in_sizes, int n_in,
                              void* d_out, int out_size)
{
    const float* x     = (const float*)d_in[0];
    const float* w1    = (const float*)d_in[1];
    const float* w2    = (const float*)d_in[2];
    const float* w3    = (const float*)d_in[3];
    const int*   langs = (const int*)  d_in[4];
    float* out = (float*)d_out;

    __half *xf, *w1f, *w3f, *w2f, *hf;
    float *p0, *p1;
    cudaGetSymbolAddress((void**)&xf,  g_xf);
    cudaGetSymbolAddress((void**)&w1f, g_w1f);
    cudaGetSymbolAddress((void**)&w3f, g_w3f);
    cudaGetSymbolAddress((void**)&w2f, g_w2f);
    cudaGetSymbolAddress((void**)&hf,  g_hf);
    cudaGetSymbolAddress((void**)&p0,  g_p0);
    cudaGetSymbolAddress((void**)&p1,  g_p1);

    cudaFuncSetAttribute(fused_gemm12_kernel,
                         cudaFuncAttributeMaxDynamicSharedMemorySize, F_SMEM);
    cudaFuncSetAttribute(gemm3_kernel,
                         cudaFuncAttributeMaxDynamicSharedMemorySize, G_SMEM);

    // 1) prep: fp16 conversions (weights expert-gated)
    {
        long nx = (long)B_ * S_ * D_ / 4;
        convert_x_kernel<<<(unsigned)(nx / 256), 256>>>(x, xf, nx);
        unsigned wb = (unsigned)(((long)D_ * F_ / 4) / 256);
        dim3 gw(wb, 3, E_);
        convert_w_kernel<<<gw, 256>>>(w1, w3, w2, w1f, w3f, w2f, langs);
    }
    // 2) fused GEMM1+GEMM2 + GLU -> h (fp16)
    {
        dim3 grid(F_ / 64, S_ / 128, B_);
        fused_gemm12_kernel<<<grid, 256, F_SMEM>>>(xf, w1f, w3f, langs, hf);
    }
    // 3) GEMM3 split-K=2 -> partials
    {
        dim3 grid(D_ / 128, S_ / 128, B_ * 2);
        gemm3_kernel<<<grid, 256, G_SMEM>>>(hf, w2f, langs, p0, p1);
    }
    // 4) reduce + routing weight
    {
        long n4 = (long)B_ * S_ * D_ / 4;
        reduce_kernel<<<(unsigned)(n4 / 256), 256>>>(p0, p1, langs, out, n4);
    }
}